// round 14
// baseline (speedup 1.0000x reference)
#include <cuda_runtime.h>
#include <cuda_fp16.h>
#include <cstdint>
#include <cmath>

#define BATCH 4
#define SEQ   2048
#define DIM   1024
#define NH    16
#define DH    64
#define MTOK  (BATCH*SEQ)
#define N1    3200
#define NQKV  3072
#define NGATE 48
#define CHUNK 64
#define NCHUNK (SEQ/CHUNK)              // 32
#define TOTCHUNK (BATCH*NH*NCHUNK)      // 2048
#define NSM_CTAS 296                    // 2 CTAs/SM x 148 SMs

// fp16 fragment-packed GEMM operands
__device__ __half2 g_xnh [MTOK * DIM / 2];    // A-fragments of rmsnormed x
__device__ __half2 g_w1h [N1 * DIM / 2];      // B-fragments of [wqkv|wgate|0]
__device__ __half2 g_w2h [DIM * DIM / 2];     // B-fragments of w_out
__device__ __half2 g_hfh [MTOK * DIM / 2];    // A-fragments of final h
// plain buffers
__device__ __half g_qkvh[MTOK * NQKV];        // qkv in fp16, [m][3072]
__device__ float  g_gt  [3 * NH * MTOK];      // gates transposed [gate][h][m]
__device__ float  g_el  [NH * MTOK];          // exp(LF_t), [h][m]
__device__ __half g_hh  [MTOK * DIM];         // h_intra (fp16)
__device__ __half g_Uh  [TOTCHUNK * 64 * 64]; // chunk increments (fp16)
__device__ __half g_Sh  [TOTCHUNK * 64 * 64]; // state before each chunk (fp16)
__device__ float  g_Fc  [TOTCHUNK];

__device__ __forceinline__ uint32_t smem_u32(const void* p) {
    return (uint32_t)__cvta_generic_to_shared(p);
}
__device__ __forceinline__ void cp16(uint32_t s, const void* g) {
    asm volatile("cp.async.cg.shared.global [%0], [%1], 16;\n" :: "r"(s), "l"(g));
}
__device__ __forceinline__ void cp_commit() {
    asm volatile("cp.async.commit_group;\n" ::: "memory");
}
template<int N> __device__ __forceinline__ void cp_wait() {
    asm volatile("cp.async.wait_group %0;\n" :: "n"(N) : "memory");
}
__device__ __forceinline__ void mma_f16(float c[4],
        uint32_t a0, uint32_t a1, uint32_t a2, uint32_t a3,
        uint32_t b0, uint32_t b1) {
    asm volatile(
        "mma.sync.aligned.m16n8k16.row.col.f32.f16.f16.f32 "
        "{%0,%1,%2,%3},{%4,%5,%6,%7},{%8,%9},{%0,%1,%2,%3};\n"
        : "+f"(c[0]), "+f"(c[1]), "+f"(c[2]), "+f"(c[3])
        : "r"(a0), "r"(a1), "r"(a2), "r"(a3), "r"(b0), "r"(b1));
}
#define FU(x) __float_as_uint(x)
__device__ __forceinline__ uint32_t H2U(__half2 v) { return *(uint32_t*)&v; }

// A-fragment half2 offset for (m, k even)
__device__ __forceinline__ size_t afrag_off(int m, int k) {
    const int mb = m >> 7, kt = k >> 5, R = (m >> 4) & 7, ks = (k >> 4) & 1;
    const int gr = m & 7, hb = (m >> 3) & 1, tg = (k & 7) >> 1, kh = (k >> 3) & 1;
    return ((((size_t)(mb * 32 + kt) * 8 + R) * 2 + ks) * 128)
         + (gr * 4 + tg) * 4 + (hb + 2 * kh);
}

// ---- prep: pack weights into fp16 B-fragment layout ----
__global__ void __launch_bounds__(256) prep_weights_kernel(
        const float* __restrict__ wqkv, const float* __restrict__ wgate,
        const float* __restrict__ wout) {
    const int P1 = N1 * DIM / 2;
    const int P2 = DIM * DIM / 2;
    const int idx = blockIdx.x * 256 + threadIdx.x;
    if (idx < P1) {
        const int kh = idx & 1, lane = (idx >> 1) & 31, ks = (idx >> 6) & 1;
        const int nbkt = idx >> 7, nb = nbkt % 400, kt = nbkt / 400;
        const int gr = lane >> 2, tg = lane & 3;
        const int n = nb * 8 + gr;
        const int k = kt * 32 + ks * 16 + kh * 8 + tg * 2;
        float v0 = 0.f, v1 = 0.f;
        if (n < NQKV)              { v0 = wqkv[k * NQKV + n];        v1 = wqkv[(k+1) * NQKV + n]; }
        else if (n < NQKV + NGATE) { v0 = wgate[k * NGATE + n-NQKV]; v1 = wgate[(k+1) * NGATE + n-NQKV]; }
        g_w1h[idx] = __floats2half2_rn(v0, v1);
    } else if (idx < P1 + P2) {
        const int j = idx - P1;
        const int kh = j & 1, lane = (j >> 1) & 31, ks = (j >> 6) & 1;
        const int nbkt = j >> 7, nb = nbkt % 128, kt = nbkt / 128;
        const int gr = lane >> 2, tg = lane & 3;
        const int n = nb * 8 + gr;
        const int k = kt * 32 + ks * 16 + kh * 8 + tg * 2;
        g_w2h[j] = __floats2half2_rn(wout[k * DIM + n], wout[(k+1) * DIM + n]);
    }
}

// ---- rmsnorm -> fp16 A-fragment layout ----
__global__ void __launch_bounds__(256) rmsnorm_kernel(
        const float* __restrict__ x, const float* __restrict__ w) {
    const int row = blockIdx.x;
    const int tid = threadIdx.x;
    const float4 xv = ((const float4*)(x + (size_t)row * DIM))[tid];
    float ss = xv.x*xv.x + xv.y*xv.y + xv.z*xv.z + xv.w*xv.w;
    #pragma unroll
    for (int off = 16; off > 0; off >>= 1)
        ss += __shfl_xor_sync(0xffffffffu, ss, off);
    __shared__ float wsum[8];
    const int lane = tid & 31, wid = tid >> 5;
    if (lane == 0) wsum[wid] = ss;
    __syncthreads();
    if (tid == 0) {
        float t = 0.f;
        #pragma unroll
        for (int i = 0; i < 8; ++i) t += wsum[i];
        wsum[0] = rsqrtf(t * (1.0f / DIM) + 1e-6f);
    }
    __syncthreads();
    const float scale = wsum[0];
    const float4 wv = ((const float4*)w)[tid];
    const int k0 = tid * 4;
    g_xnh[afrag_off(row, k0)]     = __floats2half2_rn(wv.x * (xv.x * scale), wv.y * (xv.y * scale));
    g_xnh[afrag_off(row, k0 + 2)] = __floats2half2_rn(wv.z * (xv.z * scale), wv.w * (xv.w * scale));
}

// ---- persistent fp16 GEMM: 128x128x32 tiles, 4 warps, 4-stage, 296 CTAs ----
template<int MODE>
__global__ void __launch_bounds__(128, 2) gemm_f16_kernel(
        const float* __restrict__ X, float* __restrict__ Out) {
    constexpr int KT = DIM / 32;
    constexpr int N = (MODE == 0) ? N1 : DIM;
    constexpr int NTB = N / 128;                    // tiles along n
    constexpr int TTOT = NTB * (MTOK / 128);        // total tiles
    const __half2* __restrict__ Af = (MODE == 0) ? g_xnh : g_hfh;
    const __half2* __restrict__ Bf = (MODE == 0) ? g_w1h : g_w2h;

    extern __shared__ float smem[];
    const int tid = threadIdx.x;
    const uint32_t smem_base = smem_u32(smem);
    const int lane = tid & 31, wid = tid >> 5;
    const int R0 = (wid >> 1) * 4;
    const int nb0 = (wid & 1) * 8;
    const int wm = R0 * 16, wn = nb0 * 8;
    const int gr = lane >> 2, tg = lane & 3;

    for (int t = blockIdx.x; t < TTOT; t += NSM_CTAS) {
        const int mb = t / NTB;
        const int n0 = (t - mb * NTB) * 128;
        const int m0 = mb * 128;

        auto issue = [&](int kt) {
            if (kt < KT) {
                const uint32_t st = smem_base + (uint32_t)(kt & 3) * 16384u;
                const __half2* sA = Af + (size_t)(mb * 32 + kt) * 2048;
                const __half2* sB = Bf + ((size_t)kt * (N >> 3) + (n0 >> 3)) * 128;
                #pragma unroll
                for (int q = 0; q < 4; ++q)
                    cp16(st + (uint32_t)(tid + q * 128) * 16u, sA + (tid + q * 128) * 4);
                #pragma unroll
                for (int q = 0; q < 4; ++q)
                    cp16(st + 8192u + (uint32_t)(tid + q * 128) * 16u, sB + (tid + q * 128) * 4);
            }
            cp_commit();
        };

        float acc[4][8][4];
        #pragma unroll
        for (int i = 0; i < 4; ++i)
            #pragma unroll
            for (int j = 0; j < 8; ++j)
                #pragma unroll
                for (int q = 0; q < 4; ++q) acc[i][j][q] = 0.f;

        issue(0); issue(1); issue(2);

        for (int kt = 0; kt < KT; ++kt) {
            cp_wait<2>();
            __syncthreads();
            issue(kt + 3);
            const __half2* As = (const __half2*)((const char*)smem + (kt & 3) * 16384);
            const __half2* Bs = As + 2048;
            #pragma unroll
            for (int ks = 0; ks < 2; ++ks) {
                float4 af[4]; float2 bf[8];
                #pragma unroll
                for (int i = 0; i < 4; ++i)
                    af[i] = *(const float4*)(As + ((R0 + i) * 2 + ks) * 128 + lane * 4);
                #pragma unroll
                for (int j = 0; j < 8; ++j)
                    bf[j] = *(const float2*)(Bs + ((nb0 + j) * 2 + ks) * 64 + lane * 2);
                #pragma unroll
                for (int i = 0; i < 4; ++i)
                    #pragma unroll
                    for (int j = 0; j < 8; ++j)
                        mma_f16(acc[i][j], FU(af[i].x), FU(af[i].y), FU(af[i].z), FU(af[i].w),
                                FU(bf[j].x), FU(bf[j].y));
            }
        }

        #pragma unroll
        for (int i = 0; i < 4; ++i) {
            #pragma unroll
            for (int j = 0; j < 8; ++j) {
                const int r0 = m0 + wm + i * 16 + gr;
                const int c0 = n0 + wn + j * 8 + tg * 2;
                if (MODE == 0) {
                    if (c0 < NQKV) {
                        *(__half2*)(g_qkvh + (size_t)r0 * NQKV + c0) =
                            __floats2half2_rn(acc[i][j][0], acc[i][j][1]);
                        *(__half2*)(g_qkvh + (size_t)(r0 + 8) * NQKV + c0) =
                            __floats2half2_rn(acc[i][j][2], acc[i][j][3]);
                    } else {
                        #pragma unroll
                        for (int q = 0; q < 4; ++q) {
                            const int r = r0 + (q >> 1) * 8;
                            const int c = c0 + (q & 1);
                            if (c < NQKV + NGATE) {
                                const int gl = c - NQKV;
                                float tt = tanhf(acc[i][j][q] * (1.0f / 15.0f));
                                g_gt[(size_t)gl * MTOK + r] =
                                    1.0f / (1.0f + expf(-15.0f * tt));
                            }
                        }
                    }
                } else {
                    #pragma unroll
                    for (int q = 0; q < 4; ++q) {
                        const int r = r0 + (q >> 1) * 8;
                        const int c = c0 + (q & 1);
                        Out[(size_t)r * DIM + c] = X[(size_t)r * DIM + c] + acc[i][j][q];
                    }
                }
            }
        }
    }
}

// ---- chunkwise phase 1: intra-chunk, fp16 m16n8k16 ----
#define SP 72     // half pitch
#define SP2 36    // half2 pitch
__global__ void __launch_bounds__(256) chunk_intra_kernel() {
    __shared__ __half Qh [64 * SP];   // (t,d); after GEMM1 reused as Ah (t,s)
    __shared__ __half Kh [64 * SP];   // (s,d)
    __shared__ __half Kth[64 * SP];   // (d,s) * Wc[s], col-swizzled
    __shared__ __half Vth[64 * SP];   // (e,s), col-swizzled
    __shared__ float LF[64], Wi[64], Wc[64];

    const int cidx = blockIdx.x;
    const int c = cidx & (NCHUNK - 1);
    const int bh = cidx >> 5;
    const int h = bh & 15, b = bh >> 4;
    const int m0 = b * SEQ + c * CHUNK;
    const int tid = threadIdx.x;

    float gi = 0.f, gf = 0.f;
    if (tid < 64) {
        gi = g_gt[(size_t)h * MTOK + m0 + tid];
        gf = g_gt[(size_t)(NH + h) * MTOK + m0 + tid];
    }
    uint4 hq[2], hk[2], hv[2];
    #pragma unroll
    for (int qq = 0; qq < 2; ++qq) {
        const int idx = tid + qq * 256;
        const int t = idx >> 3, d8 = (idx & 7) << 3;
        const __half* row = g_qkvh + (size_t)(m0 + t) * NQKV + h * 64 + d8;
        hq[qq] = *(const uint4*)row;
        hk[qq] = *(const uint4*)(row + 1024);
        hv[qq] = *(const uint4*)(row + 2048);
    }
    #pragma unroll
    for (int qq = 0; qq < 2; ++qq) {
        const int idx = tid + qq * 256;
        const int t = idx >> 3, d8 = (idx & 7) << 3;
        *(uint4*)(Qh + t * SP + d8) = hq[qq];
        *(uint4*)(Kh + t * SP + d8) = hk[qq];
        const __half* pv = (const __half*)&hv[qq];
        #pragma unroll
        for (int jj = 0; jj < 8; ++jj) {
            const int d = d8 + jj;
            Vth[d * SP + (t ^ (((d >> 2) & 15) << 1))] = pv[jj];
        }
    }
    if (tid < 64) { Wi[tid] = gi; LF[tid] = __logf(gf); }
    __syncthreads();

    if (tid < 32) {
        float x0 = LF[tid], x1 = LF[tid + 32];
        #pragma unroll
        for (int off = 1; off < 32; off <<= 1) {
            float y = __shfl_up_sync(0xffffffffu, x0, off);
            if (tid >= off) x0 += y;
        }
        const float tot = __shfl_sync(0xffffffffu, x0, 31);
        #pragma unroll
        for (int off = 1; off < 32; off <<= 1) {
            float y = __shfl_up_sync(0xffffffffu, x1, off);
            if (tid >= off) x1 += y;
        }
        x1 += tot;
        LF[tid] = x0; LF[tid + 32] = x1;
        g_el[(size_t)h * MTOK + m0 + tid]      = __expf(x0);
        g_el[(size_t)h * MTOK + m0 + tid + 32] = __expf(x1);
    }
    __syncthreads();
    if (tid < 64) Wc[tid] = __expf(LF[63] - LF[tid]) * Wi[tid];
    if (tid == 0) g_Fc[cidx] = __expf(LF[63]);
    __syncthreads();

    #pragma unroll
    for (int qq = 0; qq < 2; ++qq) {
        const int idx = tid + qq * 256;
        const int t = idx >> 3, d8 = (idx & 7) << 3;
        const float wcs = Wc[t];
        const __half* pk = (const __half*)&hk[qq];
        #pragma unroll
        for (int jj = 0; jj < 8; ++jj) {
            const int d = d8 + jj;
            Kth[d * SP + (t ^ (((d >> 2) & 15) << 1))] =
                __float2half(wcs * __half2float(pk[jj]));
        }
    }
    __syncthreads();

    const int lane = tid & 31, wid = tid >> 5;
    const int gr = lane >> 2, tg = lane & 3;
    const int wm = (wid >> 1) * 16, wn = (wid & 1) * 32;
    const int ra = wm + gr, rb = wm + 8 + gr;

    float acc1[4][4];
    #pragma unroll
    for (int j = 0; j < 4; ++j)
        #pragma unroll
        for (int q = 0; q < 4; ++q) acc1[j][q] = 0.f;
    {
        const __half2* Q2 = (const __half2*)Qh;
        const __half2* K2 = (const __half2*)Kh;
        #pragma unroll
        for (int ks = 0; ks < 4; ++ks) {
            const int kh2 = ks * 8 + tg;
            uint32_t a0 = H2U(Q2[ra * SP2 + kh2]);
            uint32_t a1 = H2U(Q2[rb * SP2 + kh2]);
            uint32_t a2 = H2U(Q2[ra * SP2 + kh2 + 4]);
            uint32_t a3 = H2U(Q2[rb * SP2 + kh2 + 4]);
            #pragma unroll
            for (int j = 0; j < 4; ++j) {
                const int n = wn + j * 8 + gr;
                mma_f16(acc1[j], a0, a1, a2, a3,
                        H2U(K2[n * SP2 + kh2]), H2U(K2[n * SP2 + kh2 + 4]));
            }
        }
    }
    __syncthreads();

    {
        __half* Ah = Qh;
        #pragma unroll
        for (int j = 0; j < 4; ++j)
            #pragma unroll
            for (int q = 0; q < 4; ++q) {
                const int t = wm + gr + (q >> 1) * 8;
                const int s = wn + j * 8 + tg * 2 + (q & 1);
                float v = 0.f;
                if (s <= t) v = acc1[j][q] * __expf(LF[t] - LF[s]) * Wi[s];
                Ah[t * SP + s] = __float2half(v);
            }
    }
    __syncthreads();

    float hacc[4][4], uacc[4][4];
    #pragma unroll
    for (int j = 0; j < 4; ++j)
        #pragma unroll
        for (int q = 0; q < 4; ++q) { hacc[j][q] = 0.f; uacc[j][q] = 0.f; }
    {
        const __half2* A2  = (const __half2*)Qh;
        const __half2* Kt2 = (const __half2*)Kth;
        const __half2* Vt2 = (const __half2*)Vth;
        const int swa = (ra >> 2) & 15, swb = (rb >> 2) & 15;
        #pragma unroll
        for (int ks = 0; ks < 4; ++ks) {
            const int kh2 = ks * 8 + tg;
            uint32_t ha0 = H2U(A2[ra * SP2 + kh2]);
            uint32_t ha1 = H2U(A2[rb * SP2 + kh2]);
            uint32_t ha2 = H2U(A2[ra * SP2 + kh2 + 4]);
            uint32_t ha3 = H2U(A2[rb * SP2 + kh2 + 4]);
            uint32_t ua0 = H2U(Kt2[ra * SP2 + (kh2 ^ swa)]);
            uint32_t ua1 = H2U(Kt2[rb * SP2 + (kh2 ^ swb)]);
            uint32_t ua2 = H2U(Kt2[ra * SP2 + ((kh2 + 4) ^ swa)]);
            uint32_t ua3 = H2U(Kt2[rb * SP2 + ((kh2 + 4) ^ swb)]);
            #pragma unroll
            for (int j = 0; j < 4; ++j) {
                const int n = wn + j * 8 + gr;
                const int swn = (n >> 2) & 15;
                uint32_t b0 = H2U(Vt2[n * SP2 + (kh2 ^ swn)]);
                uint32_t b1 = H2U(Vt2[n * SP2 + ((kh2 + 4) ^ swn)]);
                mma_f16(hacc[j], ha0, ha1, ha2, ha3, b0, b1);
                mma_f16(uacc[j], ua0, ua1, ua2, ua3, b0, b1);
            }
        }
    }
    #pragma unroll
    for (int j = 0; j < 4; ++j)
        #pragma unroll
        for (int qp = 0; qp < 2; ++qp) {
            const int row = wm + gr + qp * 8;
            const int col = wn + j * 8 + tg * 2;
            *(__half2*)(g_hh + (size_t)(m0 + row) * DIM + h * 64 + col) =
                __floats2half2_rn(hacc[j][qp*2], hacc[j][qp*2+1]);
            *(__half2*)(g_Uh + (size_t)cidx * 4096 + row * 64 + col) =
                __floats2half2_rn(uacc[j][qp*2], uacc[j][qp*2+1]);
        }
}

// ---- phase 2a: element-parallel state prefix (fp16 I/O, fp32 accum) ----
__global__ void __launch_bounds__(256) state_prefix_kernel(const float* __restrict__ hidden) {
    const int gid = blockIdx.x * 256 + threadIdx.x;   // 32768 threads
    const int bh = gid >> 9;
    const int off = (gid & 511) * 8;
    float S[8];
    {
        const float4 h0 = *(const float4*)(hidden + (size_t)bh * 4096 + off);
        const float4 h1 = *(const float4*)(hidden + (size_t)bh * 4096 + off + 4);
        S[0]=h0.x; S[1]=h0.y; S[2]=h0.z; S[3]=h0.w;
        S[4]=h1.x; S[5]=h1.y; S[6]=h1.z; S[7]=h1.w;
    }
    const float* fc = g_Fc + bh * NCHUNK;
    #pragma unroll 4
    for (int c = 0; c < NCHUNK; ++c) {
        const size_t p = (size_t)(bh * NCHUNK + c) * 4096 + off;
        uint4 so;
        __half2* ph = (__half2*)&so;
        #pragma unroll
        for (int e = 0; e < 4; ++e)
            ph[e] = __floats2half2_rn(S[e*2], S[e*2+1]);
        *(uint4*)(g_Sh + p) = so;
        const uint4 uu = *(const uint4*)(g_Uh + p);
        const __half2* pu = (const __half2*)&uu;
        const float F = fc[c];
        #pragma unroll
        for (int e = 0; e < 4; ++e) {
            const float2 uf = __half22float2(pu[e]);
            S[e*2]   = F * S[e*2]   + uf.x;
            S[e*2+1] = F * S[e*2+1] + uf.y;
        }
    }
}

// ---- phase 2b: h = (exp(LF)*q @ S_c + h_intra) * o, fp16 m16n8k16 ----
__global__ void __launch_bounds__(256) chunk_inter_kernel() {
    __shared__ __half Qsh[64 * SP];   // (t,d) = exp(LF_t) * q
    __shared__ __half Sth[64 * SP];   // (e,d) transposed S, col-swizzled
    __shared__ float Og[64], Eb[64];

    const int cidx = blockIdx.x;
    const int c = cidx & (NCHUNK - 1);
    const int bh = cidx >> 5;
    const int h = bh & 15, b = bh >> 4;
    const int m0 = b * SEQ + c * CHUNK;
    const int tid = threadIdx.x;

    uint4 hq[2], hs[2];
    #pragma unroll
    for (int qq = 0; qq < 2; ++qq) {
        const int idx = tid + qq * 256;
        const int t = idx >> 3, d8 = (idx & 7) << 3;
        hq[qq] = *(const uint4*)(g_qkvh + (size_t)(m0 + t) * NQKV + h * 64 + d8);
        hs[qq] = *(const uint4*)(g_Sh + (size_t)cidx * 4096 + t * 64 + d8);
    }
    if (tid < 64) {
        Og[tid] = g_gt[(size_t)(2 * NH + h) * MTOK + m0 + tid];
        Eb[tid] = g_el[(size_t)h * MTOK + m0 + tid];
    }
    __syncthreads();

    #pragma unroll
    for (int qq = 0; qq < 2; ++qq) {
        const int idx = tid + qq * 256;
        const int t = idx >> 3, d8 = (idx & 7) << 3;
        {
            const float e = Eb[t];
            const __half2* pq = (const __half2*)&hq[qq];
            __half2* dst = (__half2*)(Qsh + t * SP + d8);
            #pragma unroll
            for (int jj = 0; jj < 4; ++jj) {
                float2 f = __half22float2(pq[jj]);
                dst[jj] = __floats2half2_rn(f.x * e, f.y * e);
            }
        }
        {
            const int d = t;
            const __half* ps = (const __half*)&hs[qq];
            #pragma unroll
            for (int jj = 0; jj < 8; ++jj) {
                const int e = d8 + jj;
                Sth[e * SP + (d ^ (((e >> 2) & 15) << 1))] = ps[jj];
            }
        }
    }
    __syncthreads();

    const int lane = tid & 31, wid = tid >> 5;
    const int gr = lane >> 2, tg = lane & 3;
    const int wm = (wid >> 1) * 16, wn = (wid & 1) * 32;
    const int ra = wm + gr, rb = wm + 8 + gr;

    float acc[4][4];
    #pragma unroll
    for (int j = 0; j < 4; ++j)
        #pragma unroll
        for (int q = 0; q < 4; ++q) acc[j][q] = 0.f;
    {
        const __half2* Q2 = (const __half2*)Qsh;
        const __half2* St2 = (const __half2*)Sth;
        #pragma unroll
        for (int ks = 0; ks < 4; ++ks) {
            const int kh2 = ks * 8 + tg;
            uint32_t a0 = H2U(Q2[ra * SP2 + kh2]);
            uint32_t a1 = H2U(Q2[rb * SP2 + kh2]);
            uint32_t a2 = H2U(Q2[ra * SP2 + kh2 + 4]);
            uint32_t a3 = H2U(Q2[rb * SP2 + kh2 + 4]);
            #pragma unroll
            for (int j = 0; j < 4; ++j) {
                const int n = wn + j * 8 + gr;
                const int swn = (n >> 2) & 15;
                mma_f16(acc[j], a0, a1, a2, a3,
                        H2U(St2[n * SP2 + (kh2 ^ swn)]),
                        H2U(St2[n * SP2 + ((kh2 + 4) ^ swn)]));
            }
        }
    }

    #pragma unroll
    for (int j = 0; j < 4; ++j)
        #pragma unroll
        for (int qp = 0; qp < 2; ++qp) {
            const int row = wm + gr + qp * 8;
            const int col = wn + j * 8 + tg * 2;
            const int m = m0 + row;
            const float og = Og[row];
            const float2 hi = __half22float2(
                *(const __half2*)(g_hh + (size_t)m * DIM + h * 64 + col));
            const float hv0 = (acc[j][qp*2]   + hi.x) * og;
            const float hv1 = (acc[j][qp*2+1] + hi.y) * og;
            g_hfh[afrag_off(m, h * 64 + col)] = __floats2half2_rn(hv0, hv1);
        }
}

extern "C" void kernel_launch(void* const* d_in, const int* in_sizes, int n_in,
                              void* d_out, int out_size) {
    const float* x      = (const float*)d_in[0];
    const float* hidden = (const float*)d_in[1];
    const float* w_rms  = (const float*)d_in[2];
    const float* w_qkv  = (const float*)d_in[3];
    const float* w_gate = (const float*)d_in[4];
    const float* w_out  = (const float*)d_in[5];
    float* out = (float*)d_out;

    static bool attr_done = false;
    if (!attr_done) {
        cudaFuncSetAttribute(gemm_f16_kernel<0>,
            cudaFuncAttributeMaxDynamicSharedMemorySize, 65536);
        cudaFuncSetAttribute(gemm_f16_kernel<1>,
            cudaFuncAttributeMaxDynamicSharedMemorySize, 65536);
        attr_done = true;
    }

    const int PAIRS = N1 * DIM / 2 + DIM * DIM / 2;
    prep_weights_kernel<<<(PAIRS + 255) / 256, 256>>>(w_qkv, w_gate, w_out);
    rmsnorm_kernel<<<MTOK, 256>>>(x, w_rms);
    gemm_f16_kernel<0><<<NSM_CTAS, 128, 65536>>>(nullptr, nullptr);
    chunk_intra_kernel<<<TOTCHUNK, 256>>>();
    state_prefix_kernel<<<128, 256>>>(hidden);
    chunk_inter_kernel<<<TOTCHUNK, 256>>>();
    gemm_f16_kernel<1><<<NSM_CTAS, 128, 65536>>>(x, out);
}

// round 15
// speedup vs baseline: 1.0182x; 1.0182x over previous
#include <cuda_runtime.h>
#include <cuda_fp16.h>
#include <cstdint>
#include <cmath>

#define BATCH 4
#define SEQ   2048
#define DIM   1024
#define NH    16
#define DH    64
#define MTOK  (BATCH*SEQ)
#define N1    3200
#define NQKV  3072
#define NGATE 48
#define CHUNK 64
#define NCHUNK (SEQ/CHUNK)              // 32
#define TOTCHUNK (BATCH*NH*NCHUNK)      // 2048
#define PREP_BLOCKS 8448                // (N1*DIM/2 + DIM*DIM/2) / 256

// fp16 fragment-packed GEMM operands
__device__ __half2 g_xnh [MTOK * DIM / 2];    // A-fragments of rmsnormed x
__device__ __half2 g_w1h [N1 * DIM / 2];      // B-fragments of [wqkv|wgate|0]
__device__ __half2 g_w2h [DIM * DIM / 2];     // B-fragments of w_out
__device__ __half2 g_hfh [MTOK * DIM / 2];    // A-fragments of final h
// plain buffers
__device__ __half g_qkvh[MTOK * NQKV];        // qkv in fp16, [m][3072]
__device__ float  g_gt  [3 * NH * MTOK];      // gates transposed [gate][h][m]
__device__ float  g_el  [NH * MTOK];          // exp(LF_t), [h][m]
__device__ __half g_hh  [MTOK * DIM];         // h_intra (fp16)
__device__ __half g_Uh  [TOTCHUNK * 64 * 64]; // chunk increments (fp16)
__device__ __half g_Sh  [TOTCHUNK * 64 * 64]; // state before each chunk (fp16)
__device__ float  g_Fc  [TOTCHUNK];

__device__ __forceinline__ uint32_t smem_u32(const void* p) {
    return (uint32_t)__cvta_generic_to_shared(p);
}
__device__ __forceinline__ void cp16(uint32_t s, const void* g) {
    asm volatile("cp.async.cg.shared.global [%0], [%1], 16;\n" :: "r"(s), "l"(g));
}
__device__ __forceinline__ void cp_commit() {
    asm volatile("cp.async.commit_group;\n" ::: "memory");
}
template<int N> __device__ __forceinline__ void cp_wait() {
    asm volatile("cp.async.wait_group %0;\n" :: "n"(N) : "memory");
}
__device__ __forceinline__ void mma_f16(float c[4],
        uint32_t a0, uint32_t a1, uint32_t a2, uint32_t a3,
        uint32_t b0, uint32_t b1) {
    asm volatile(
        "mma.sync.aligned.m16n8k16.row.col.f32.f16.f16.f32 "
        "{%0,%1,%2,%3},{%4,%5,%6,%7},{%8,%9},{%0,%1,%2,%3};\n"
        : "+f"(c[0]), "+f"(c[1]), "+f"(c[2]), "+f"(c[3])
        : "r"(a0), "r"(a1), "r"(a2), "r"(a3), "r"(b0), "r"(b1));
}
#define FU(x) __float_as_uint(x)
__device__ __forceinline__ uint32_t H2U(__half2 v) { return *(uint32_t*)&v; }

// A-fragment half2 offset for (m, k even)
__device__ __forceinline__ size_t afrag_off(int m, int k) {
    const int mb = m >> 7, kt = k >> 5, R = (m >> 4) & 7, ks = (k >> 4) & 1;
    const int gr = m & 7, hb = (m >> 3) & 1, tg = (k & 7) >> 1, kh = (k >> 3) & 1;
    return ((((size_t)(mb * 32 + kt) * 8 + R) * 2 + ks) * 128)
         + (gr * 4 + tg) * 4 + (hb + 2 * kh);
}

// ---- fused startup: rmsnorm (blocks 0..MTOK-1) + weight prep (rest) ----
__global__ void __launch_bounds__(256) startup_kernel(
        const float* __restrict__ x, const float* __restrict__ w,
        const float* __restrict__ wqkv, const float* __restrict__ wgate,
        const float* __restrict__ wout) {
    const int tid = threadIdx.x;
    if (blockIdx.x < MTOK) {
        // ---------- rmsnorm row ----------
        const int row = blockIdx.x;
        const float4 xv = ((const float4*)(x + (size_t)row * DIM))[tid];
        float ss = xv.x*xv.x + xv.y*xv.y + xv.z*xv.z + xv.w*xv.w;
        #pragma unroll
        for (int off = 16; off > 0; off >>= 1)
            ss += __shfl_xor_sync(0xffffffffu, ss, off);
        __shared__ float wsum[8];
        const int lane = tid & 31, wid = tid >> 5;
        if (lane == 0) wsum[wid] = ss;
        __syncthreads();
        if (tid == 0) {
            float t = 0.f;
            #pragma unroll
            for (int i = 0; i < 8; ++i) t += wsum[i];
            wsum[0] = rsqrtf(t * (1.0f / DIM) + 1e-6f);
        }
        __syncthreads();
        const float scale = wsum[0];
        const float4 wv = ((const float4*)w)[tid];
        const int k0 = tid * 4;
        g_xnh[afrag_off(row, k0)]     = __floats2half2_rn(wv.x * (xv.x * scale), wv.y * (xv.y * scale));
        g_xnh[afrag_off(row, k0 + 2)] = __floats2half2_rn(wv.z * (xv.z * scale), wv.w * (xv.w * scale));
    } else {
        // ---------- weight prep ----------
        const int P1 = N1 * DIM / 2;
        const int P2 = DIM * DIM / 2;
        const int idx = (blockIdx.x - MTOK) * 256 + tid;
        if (idx < P1) {
            const int kh = idx & 1, lane = (idx >> 1) & 31, ks = (idx >> 6) & 1;
            const int nbkt = idx >> 7, nb = nbkt % 400, kt = nbkt / 400;
            const int gr = lane >> 2, tg = lane & 3;
            const int n = nb * 8 + gr;
            const int k = kt * 32 + ks * 16 + kh * 8 + tg * 2;
            float v0 = 0.f, v1 = 0.f;
            if (n < NQKV)              { v0 = wqkv[k * NQKV + n];        v1 = wqkv[(k+1) * NQKV + n]; }
            else if (n < NQKV + NGATE) { v0 = wgate[k * NGATE + n-NQKV]; v1 = wgate[(k+1) * NGATE + n-NQKV]; }
            g_w1h[idx] = __floats2half2_rn(v0, v1);
        } else if (idx < P1 + P2) {
            const int j = idx - P1;
            const int kh = j & 1, lane = (j >> 1) & 31, ks = (j >> 6) & 1;
            const int nbkt = j >> 7, nb = nbkt % 128, kt = nbkt / 128;
            const int gr = lane >> 2, tg = lane & 3;
            const int n = nb * 8 + gr;
            const int k = kt * 32 + ks * 16 + kh * 8 + tg * 2;
            g_w2h[j] = __floats2half2_rn(wout[k * DIM + n], wout[(k+1) * DIM + n]);
        }
    }
}

// ---- fp16 fragment-packed GEMM: 128x128x32 tiles, 4 warps of 64x64, 4-stage ----
template<int MODE>
__global__ void __launch_bounds__(128, 2) gemm_f16_kernel(
        const float* __restrict__ X, float* __restrict__ Out) {
    constexpr int KT = DIM / 32;
    constexpr int N = (MODE == 0) ? N1 : DIM;
    const __half2* __restrict__ Af = (MODE == 0) ? g_xnh : g_hfh;
    const __half2* __restrict__ Bf = (MODE == 0) ? g_w1h : g_w2h;

    extern __shared__ float smem[];
    const int tid = threadIdx.x;
    const int mb = blockIdx.y, n0 = blockIdx.x * 128;
    const int m0 = mb * 128;
    const uint32_t smem_base = smem_u32(smem);

    auto issue = [&](int kt) {
        if (kt < KT) {
            const uint32_t st = smem_base + (uint32_t)(kt & 3) * 16384u;
            const __half2* sA = Af + (size_t)(mb * 32 + kt) * 2048;
            const __half2* sB = Bf + ((size_t)kt * (N >> 3) + (n0 >> 3)) * 128;
            #pragma unroll
            for (int q = 0; q < 4; ++q)
                cp16(st + (uint32_t)(tid + q * 128) * 16u, sA + (tid + q * 128) * 4);
            #pragma unroll
            for (int q = 0; q < 4; ++q)
                cp16(st + 8192u + (uint32_t)(tid + q * 128) * 16u, sB + (tid + q * 128) * 4);
        }
        cp_commit();
    };

    float acc[4][8][4];
    #pragma unroll
    for (int i = 0; i < 4; ++i)
        #pragma unroll
        for (int j = 0; j < 8; ++j)
            #pragma unroll
            for (int q = 0; q < 4; ++q) acc[i][j][q] = 0.f;

    issue(0); issue(1); issue(2);

    const int lane = tid & 31, wid = tid >> 5;
    const int R0 = (wid >> 1) * 4;
    const int nb0 = (wid & 1) * 8;
    const int wm = R0 * 16, wn = nb0 * 8;
    const int gr = lane >> 2, tg = lane & 3;

    for (int kt = 0; kt < KT; ++kt) {
        cp_wait<2>();
        __syncthreads();
        issue(kt + 3);
        const __half2* As = (const __half2*)((const char*)smem + (kt & 3) * 16384);
        const __half2* Bs = As + 2048;
        #pragma unroll
        for (int ks = 0; ks < 2; ++ks) {
            float4 af[4]; float2 bf[8];
            #pragma unroll
            for (int i = 0; i < 4; ++i)
                af[i] = *(const float4*)(As + ((R0 + i) * 2 + ks) * 128 + lane * 4);
            #pragma unroll
            for (int j = 0; j < 8; ++j)
                bf[j] = *(const float2*)(Bs + ((nb0 + j) * 2 + ks) * 64 + lane * 2);
            #pragma unroll
            for (int i = 0; i < 4; ++i)
                #pragma unroll
                for (int j = 0; j < 8; ++j)
                    mma_f16(acc[i][j], FU(af[i].x), FU(af[i].y), FU(af[i].z), FU(af[i].w),
                            FU(bf[j].x), FU(bf[j].y));
        }
    }

    #pragma unroll
    for (int i = 0; i < 4; ++i) {
        #pragma unroll
        for (int j = 0; j < 8; ++j) {
            const int r0 = m0 + wm + i * 16 + gr;
            const int c0 = n0 + wn + j * 8 + tg * 2;
            if (MODE == 0) {
                if (c0 < NQKV) {
                    *(__half2*)(g_qkvh + (size_t)r0 * NQKV + c0) =
                        __floats2half2_rn(acc[i][j][0], acc[i][j][1]);
                    *(__half2*)(g_qkvh + (size_t)(r0 + 8) * NQKV + c0) =
                        __floats2half2_rn(acc[i][j][2], acc[i][j][3]);
                } else {
                    #pragma unroll
                    for (int q = 0; q < 4; ++q) {
                        const int r = r0 + (q >> 1) * 8;
                        const int c = c0 + (q & 1);
                        if (c < NQKV + NGATE) {
                            const int gl = c - NQKV;
                            float tt = tanhf(acc[i][j][q] * (1.0f / 15.0f));
                            g_gt[(size_t)gl * MTOK + r] =
                                1.0f / (1.0f + expf(-15.0f * tt));
                        }
                    }
                }
            } else {
                #pragma unroll
                for (int q = 0; q < 4; ++q) {
                    const int r = r0 + (q >> 1) * 8;
                    const int c = c0 + (q & 1);
                    Out[(size_t)r * DIM + c] = X[(size_t)r * DIM + c] + acc[i][j][q];
                }
            }
        }
    }
}

// ---- chunkwise phase 1: intra-chunk, fp16 m16n8k16 ----
#define SP 72     // half pitch
#define SP2 36    // half2 pitch
__global__ void __launch_bounds__(256) chunk_intra_kernel() {
    __shared__ __half Qh [64 * SP];   // (t,d); after GEMM1 reused as Ah (t,s)
    __shared__ __half Kh [64 * SP];   // (s,d)
    __shared__ __half Kth[64 * SP];   // (d,s) * Wc[s], col-swizzled
    __shared__ __half Vth[64 * SP];   // (e,s), col-swizzled
    __shared__ float LF[64], Wi[64], Wc[64];

    const int cidx = blockIdx.x;
    const int c = cidx & (NCHUNK - 1);
    const int bh = cidx >> 5;
    const int h = bh & 15, b = bh >> 4;
    const int m0 = b * SEQ + c * CHUNK;
    const int tid = threadIdx.x;

    float gi = 0.f, gf = 0.f;
    if (tid < 64) {
        gi = g_gt[(size_t)h * MTOK + m0 + tid];
        gf = g_gt[(size_t)(NH + h) * MTOK + m0 + tid];
    }
    uint4 hq[2], hk[2], hv[2];
    #pragma unroll
    for (int qq = 0; qq < 2; ++qq) {
        const int idx = tid + qq * 256;
        const int t = idx >> 3, d8 = (idx & 7) << 3;
        const __half* row = g_qkvh + (size_t)(m0 + t) * NQKV + h * 64 + d8;
        hq[qq] = *(const uint4*)row;
        hk[qq] = *(const uint4*)(row + 1024);
        hv[qq] = *(const uint4*)(row + 2048);
    }
    #pragma unroll
    for (int qq = 0; qq < 2; ++qq) {
        const int idx = tid + qq * 256;
        const int t = idx >> 3, d8 = (idx & 7) << 3;
        *(uint4*)(Qh + t * SP + d8) = hq[qq];
        *(uint4*)(Kh + t * SP + d8) = hk[qq];
        const __half* pv = (const __half*)&hv[qq];
        #pragma unroll
        for (int jj = 0; jj < 8; ++jj) {
            const int d = d8 + jj;
            Vth[d * SP + (t ^ (((d >> 2) & 15) << 1))] = pv[jj];
        }
    }
    if (tid < 64) { Wi[tid] = gi; LF[tid] = __logf(gf); }
    __syncthreads();

    if (tid < 32) {
        float x0 = LF[tid], x1 = LF[tid + 32];
        #pragma unroll
        for (int off = 1; off < 32; off <<= 1) {
            float y = __shfl_up_sync(0xffffffffu, x0, off);
            if (tid >= off) x0 += y;
        }
        const float tot = __shfl_sync(0xffffffffu, x0, 31);
        #pragma unroll
        for (int off = 1; off < 32; off <<= 1) {
            float y = __shfl_up_sync(0xffffffffu, x1, off);
            if (tid >= off) x1 += y;
        }
        x1 += tot;
        LF[tid] = x0; LF[tid + 32] = x1;
        g_el[(size_t)h * MTOK + m0 + tid]      = __expf(x0);
        g_el[(size_t)h * MTOK + m0 + tid + 32] = __expf(x1);
    }
    __syncthreads();
    if (tid < 64) Wc[tid] = __expf(LF[63] - LF[tid]) * Wi[tid];
    if (tid == 0) g_Fc[cidx] = __expf(LF[63]);
    __syncthreads();

    #pragma unroll
    for (int qq = 0; qq < 2; ++qq) {
        const int idx = tid + qq * 256;
        const int t = idx >> 3, d8 = (idx & 7) << 3;
        const float wcs = Wc[t];
        const __half* pk = (const __half*)&hk[qq];
        #pragma unroll
        for (int jj = 0; jj < 8; ++jj) {
            const int d = d8 + jj;
            Kth[d * SP + (t ^ (((d >> 2) & 15) << 1))] =
                __float2half(wcs * __half2float(pk[jj]));
        }
    }
    __syncthreads();

    const int lane = tid & 31, wid = tid >> 5;
    const int gr = lane >> 2, tg = lane & 3;
    const int wm = (wid >> 1) * 16, wn = (wid & 1) * 32;
    const int ra = wm + gr, rb = wm + 8 + gr;

    float acc1[4][4];
    #pragma unroll
    for (int j = 0; j < 4; ++j)
        #pragma unroll
        for (int q = 0; q < 4; ++q) acc1[j][q] = 0.f;
    {
        const __half2* Q2 = (const __half2*)Qh;
        const __half2* K2 = (const __half2*)Kh;
        #pragma unroll
        for (int ks = 0; ks < 4; ++ks) {
            const int kh2 = ks * 8 + tg;
            uint32_t a0 = H2U(Q2[ra * SP2 + kh2]);
            uint32_t a1 = H2U(Q2[rb * SP2 + kh2]);
            uint32_t a2 = H2U(Q2[ra * SP2 + kh2 + 4]);
            uint32_t a3 = H2U(Q2[rb * SP2 + kh2 + 4]);
            #pragma unroll
            for (int j = 0; j < 4; ++j) {
                const int n = wn + j * 8 + gr;
                mma_f16(acc1[j], a0, a1, a2, a3,
                        H2U(K2[n * SP2 + kh2]), H2U(K2[n * SP2 + kh2 + 4]));
            }
        }
    }
    __syncthreads();

    {
        __half* Ah = Qh;
        #pragma unroll
        for (int j = 0; j < 4; ++j)
            #pragma unroll
            for (int q = 0; q < 4; ++q) {
                const int t = wm + gr + (q >> 1) * 8;
                const int s = wn + j * 8 + tg * 2 + (q & 1);
                float v = 0.f;
                if (s <= t) v = acc1[j][q] * __expf(LF[t] - LF[s]) * Wi[s];
                Ah[t * SP + s] = __float2half(v);
            }
    }
    __syncthreads();

    float hacc[4][4], uacc[4][4];
    #pragma unroll
    for (int j = 0; j < 4; ++j)
        #pragma unroll
        for (int q = 0; q < 4; ++q) { hacc[j][q] = 0.f; uacc[j][q] = 0.f; }
    {
        const __half2* A2  = (const __half2*)Qh;
        const __half2* Kt2 = (const __half2*)Kth;
        const __half2* Vt2 = (const __half2*)Vth;
        const int swa = (ra >> 2) & 15, swb = (rb >> 2) & 15;
        #pragma unroll
        for (int ks = 0; ks < 4; ++ks) {
            const int kh2 = ks * 8 + tg;
            uint32_t ha0 = H2U(A2[ra * SP2 + kh2]);
            uint32_t ha1 = H2U(A2[rb * SP2 + kh2]);
            uint32_t ha2 = H2U(A2[ra * SP2 + kh2 + 4]);
            uint32_t ha3 = H2U(A2[rb * SP2 + kh2 + 4]);
            uint32_t ua0 = H2U(Kt2[ra * SP2 + (kh2 ^ swa)]);
            uint32_t ua1 = H2U(Kt2[rb * SP2 + (kh2 ^ swb)]);
            uint32_t ua2 = H2U(Kt2[ra * SP2 + ((kh2 + 4) ^ swa)]);
            uint32_t ua3 = H2U(Kt2[rb * SP2 + ((kh2 + 4) ^ swb)]);
            #pragma unroll
            for (int j = 0; j < 4; ++j) {
                const int n = wn + j * 8 + gr;
                const int swn = (n >> 2) & 15;
                uint32_t b0 = H2U(Vt2[n * SP2 + (kh2 ^ swn)]);
                uint32_t b1 = H2U(Vt2[n * SP2 + ((kh2 + 4) ^ swn)]);
                mma_f16(hacc[j], ha0, ha1, ha2, ha3, b0, b1);
                mma_f16(uacc[j], ua0, ua1, ua2, ua3, b0, b1);
            }
        }
    }
    #pragma unroll
    for (int j = 0; j < 4; ++j)
        #pragma unroll
        for (int qp = 0; qp < 2; ++qp) {
            const int row = wm + gr + qp * 8;
            const int col = wn + j * 8 + tg * 2;
            *(__half2*)(g_hh + (size_t)(m0 + row) * DIM + h * 64 + col) =
                __floats2half2_rn(hacc[j][qp*2], hacc[j][qp*2+1]);
            *(__half2*)(g_Uh + (size_t)cidx * 4096 + row * 64 + col) =
                __floats2half2_rn(uacc[j][qp*2], uacc[j][qp*2+1]);
        }
}

// ---- phase 2a: element-parallel state prefix (fp16 I/O, fp32 accum) ----
__global__ void __launch_bounds__(256) state_prefix_kernel(const float* __restrict__ hidden) {
    const int gid = blockIdx.x * 256 + threadIdx.x;   // 32768 threads
    const int bh = gid >> 9;
    const int off = (gid & 511) * 8;
    float S[8];
    {
        const float4 h0 = *(const float4*)(hidden + (size_t)bh * 4096 + off);
        const float4 h1 = *(const float4*)(hidden + (size_t)bh * 4096 + off + 4);
        S[0]=h0.x; S[1]=h0.y; S[2]=h0.z; S[3]=h0.w;
        S[4]=h1.x; S[5]=h1.y; S[6]=h1.z; S[7]=h1.w;
    }
    const float* fc = g_Fc + bh * NCHUNK;
    #pragma unroll 4
    for (int c = 0; c < NCHUNK; ++c) {
        const size_t p = (size_t)(bh * NCHUNK + c) * 4096 + off;
        uint4 so;
        __half2* ph = (__half2*)&so;
        #pragma unroll
        for (int e = 0; e < 4; ++e)
            ph[e] = __floats2half2_rn(S[e*2], S[e*2+1]);
        *(uint4*)(g_Sh + p) = so;
        const uint4 uu = *(const uint4*)(g_Uh + p);
        const __half2* pu = (const __half2*)&uu;
        const float F = fc[c];
        #pragma unroll
        for (int e = 0; e < 4; ++e) {
            const float2 uf = __half22float2(pu[e]);
            S[e*2]   = F * S[e*2]   + uf.x;
            S[e*2+1] = F * S[e*2+1] + uf.y;
        }
    }
}

// ---- phase 2b: h = (exp(LF)*q @ S_c + h_intra) * o, fp16 m16n8k16 ----
__global__ void __launch_bounds__(256) chunk_inter_kernel() {
    __shared__ __half Qsh[64 * SP];   // (t,d) = exp(LF_t) * q
    __shared__ __half Sth[64 * SP];   // (e,d) transposed S, col-swizzled
    __shared__ float Og[64], Eb[64];

    const int cidx = blockIdx.x;
    const int c = cidx & (NCHUNK - 1);
    const int bh = cidx >> 5;
    const int h = bh & 15, b = bh >> 4;
    const int m0 = b * SEQ + c * CHUNK;
    const int tid = threadIdx.x;

    uint4 hq[2], hs[2];
    #pragma unroll
    for (int qq = 0; qq < 2; ++qq) {
        const int idx = tid + qq * 256;
        const int t = idx >> 3, d8 = (idx & 7) << 3;
        hq[qq] = *(const uint4*)(g_qkvh + (size_t)(m0 + t) * NQKV + h * 64 + d8);
        hs[qq] = *(const uint4*)(g_Sh + (size_t)cidx * 4096 + t * 64 + d8);
    }
    if (tid < 64) {
        Og[tid] = g_gt[(size_t)(2 * NH + h) * MTOK + m0 + tid];
        Eb[tid] = g_el[(size_t)h * MTOK + m0 + tid];
    }
    __syncthreads();

    #pragma unroll
    for (int qq = 0; qq < 2; ++qq) {
        const int idx = tid + qq * 256;
        const int t = idx >> 3, d8 = (idx & 7) << 3;
        {
            const float e = Eb[t];
            const __half2* pq = (const __half2*)&hq[qq];
            __half2* dst = (__half2*)(Qsh + t * SP + d8);
            #pragma unroll
            for (int jj = 0; jj < 4; ++jj) {
                float2 f = __half22float2(pq[jj]);
                dst[jj] = __floats2half2_rn(f.x * e, f.y * e);
            }
        }
        {
            const int d = t;
            const __half* ps = (const __half*)&hs[qq];
            #pragma unroll
            for (int jj = 0; jj < 8; ++jj) {
                const int e = d8 + jj;
                Sth[e * SP + (d ^ (((e >> 2) & 15) << 1))] = ps[jj];
            }
        }
    }
    __syncthreads();

    const int lane = tid & 31, wid = tid >> 5;
    const int gr = lane >> 2, tg = lane & 3;
    const int wm = (wid >> 1) * 16, wn = (wid & 1) * 32;
    const int ra = wm + gr, rb = wm + 8 + gr;

    float acc[4][4];
    #pragma unroll
    for (int j = 0; j < 4; ++j)
        #pragma unroll
        for (int q = 0; q < 4; ++q) acc[j][q] = 0.f;
    {
        const __half2* Q2 = (const __half2*)Qsh;
        const __half2* St2 = (const __half2*)Sth;
        #pragma unroll
        for (int ks = 0; ks < 4; ++ks) {
            const int kh2 = ks * 8 + tg;
            uint32_t a0 = H2U(Q2[ra * SP2 + kh2]);
            uint32_t a1 = H2U(Q2[rb * SP2 + kh2]);
            uint32_t a2 = H2U(Q2[ra * SP2 + kh2 + 4]);
            uint32_t a3 = H2U(Q2[rb * SP2 + kh2 + 4]);
            #pragma unroll
            for (int j = 0; j < 4; ++j) {
                const int n = wn + j * 8 + gr;
                const int swn = (n >> 2) & 15;
                mma_f16(acc[j], a0, a1, a2, a3,
                        H2U(St2[n * SP2 + (kh2 ^ swn)]),
                        H2U(St2[n * SP2 + ((kh2 + 4) ^ swn)]));
            }
        }
    }

    #pragma unroll
    for (int j = 0; j < 4; ++j)
        #pragma unroll
        for (int qp = 0; qp < 2; ++qp) {
            const int row = wm + gr + qp * 8;
            const int col = wn + j * 8 + tg * 2;
            const int m = m0 + row;
            const float og = Og[row];
            const float2 hi = __half22float2(
                *(const __half2*)(g_hh + (size_t)m * DIM + h * 64 + col));
            const float hv0 = (acc[j][qp*2]   + hi.x) * og;
            const float hv1 = (acc[j][qp*2+1] + hi.y) * og;
            g_hfh[afrag_off(m, h * 64 + col)] = __floats2half2_rn(hv0, hv1);
        }
}

extern "C" void kernel_launch(void* const* d_in, const int* in_sizes, int n_in,
                              void* d_out, int out_size) {
    const float* x      = (const float*)d_in[0];
    const float* hidden = (const float*)d_in[1];
    const float* w_rms  = (const float*)d_in[2];
    const float* w_qkv  = (const float*)d_in[3];
    const float* w_gate = (const float*)d_in[4];
    const float* w_out  = (const float*)d_in[5];
    float* out = (float*)d_out;

    static bool attr_done = false;
    if (!attr_done) {
        cudaFuncSetAttribute(gemm_f16_kernel<0>,
            cudaFuncAttributeMaxDynamicSharedMemorySize, 65536);
        cudaFuncSetAttribute(gemm_f16_kernel<1>,
            cudaFuncAttributeMaxDynamicSharedMemorySize, 65536);
        attr_done = true;
    }

    startup_kernel<<<MTOK + PREP_BLOCKS, 256>>>(x, w_rms, w_qkv, w_gate, w_out);
    {
        dim3 grid(N1 / 128, MTOK / 128);
        gemm_f16_kernel<0><<<grid, 128, 65536>>>(nullptr, nullptr);
    }
    chunk_intra_kernel<<<TOTCHUNK, 256>>>();
    state_prefix_kernel<<<128, 256>>>(hidden);
    chunk_inter_kernel<<<TOTCHUNK, 256>>>();
    {
        dim3 grid(DIM / 128, MTOK / 128);
        gemm_f16_kernel<1><<<grid, 128, 65536>>>(x, out);
    }
}

// round 16
// speedup vs baseline: 1.0204x; 1.0022x over previous
#include <cuda_runtime.h>
#include <cuda_fp16.h>
#include <cstdint>
#include <cmath>

#define BATCH 4
#define SEQ   2048
#define DIM   1024
#define NH    16
#define DH    64
#define MTOK  (BATCH*SEQ)
#define N1    3200
#define NQKV  3072
#define NGATE 48
#define CHUNK 64
#define NCHUNK (SEQ/CHUNK)              // 32
#define TOTCHUNK (BATCH*NH*NCHUNK)      // 2048
#define PREP_BLOCKS 8448                // (N1*DIM/2 + DIM*DIM/2) / 256

// fp16 fragment-packed GEMM operands
__device__ __half2 g_xnh [MTOK * DIM / 2];    // A-fragments of rmsnormed x
__device__ __half2 g_w1h [N1 * DIM / 2];      // B-fragments of [wqkv|wgate|0]
__device__ __half2 g_w2h [DIM * DIM / 2];     // B-fragments of w_out
__device__ __half2 g_hfh [MTOK * DIM / 2];    // A-fragments of final h
// plain buffers
__device__ __half g_qkvh[MTOK * NQKV];        // qkv in fp16, [m][3072]
__device__ float  g_gt  [3 * NH * MTOK];      // gates transposed [gate][h][m]
__device__ float  g_el  [NH * MTOK];          // exp(LF_t), [h][m]
__device__ __half g_hh  [MTOK * DIM];         // h_intra (fp16)
__device__ __half g_Uh  [TOTCHUNK * 64 * 64]; // chunk increments (fp16)
__device__ __half g_Sh  [TOTCHUNK * 64 * 64]; // state before each chunk (fp16)
__device__ float  g_Fc  [TOTCHUNK];

__device__ __forceinline__ uint32_t smem_u32(const void* p) {
    return (uint32_t)__cvta_generic_to_shared(p);
}
__device__ __forceinline__ void cp16(uint32_t s, const void* g) {
    asm volatile("cp.async.cg.shared.global [%0], [%1], 16;\n" :: "r"(s), "l"(g));
}
__device__ __forceinline__ void cp_commit() {
    asm volatile("cp.async.commit_group;\n" ::: "memory");
}
template<int N> __device__ __forceinline__ void cp_wait() {
    asm volatile("cp.async.wait_group %0;\n" :: "n"(N) : "memory");
}
__device__ __forceinline__ void mma_f16(float c[4],
        uint32_t a0, uint32_t a1, uint32_t a2, uint32_t a3,
        uint32_t b0, uint32_t b1) {
    asm volatile(
        "mma.sync.aligned.m16n8k16.row.col.f32.f16.f16.f32 "
        "{%0,%1,%2,%3},{%4,%5,%6,%7},{%8,%9},{%0,%1,%2,%3};\n"
        : "+f"(c[0]), "+f"(c[1]), "+f"(c[2]), "+f"(c[3])
        : "r"(a0), "r"(a1), "r"(a2), "r"(a3), "r"(b0), "r"(b1));
}
#define FU(x) __float_as_uint(x)
__device__ __forceinline__ uint32_t H2U(__half2 v) { return *(uint32_t*)&v; }

// A-fragment half2 offset for (m, k even)
__device__ __forceinline__ size_t afrag_off(int m, int k) {
    const int mb = m >> 7, kt = k >> 5, R = (m >> 4) & 7, ks = (k >> 4) & 1;
    const int gr = m & 7, hb = (m >> 3) & 1, tg = (k & 7) >> 1, kh = (k >> 3) & 1;
    return ((((size_t)(mb * 32 + kt) * 8 + R) * 2 + ks) * 128)
         + (gr * 4 + tg) * 4 + (hb + 2 * kh);
}

// ---- fused startup: rmsnorm (blocks 0..MTOK-1) + weight prep (rest) ----
__global__ void __launch_bounds__(256) startup_kernel(
        const float* __restrict__ x, const float* __restrict__ w,
        const float* __restrict__ wqkv, const float* __restrict__ wgate,
        const float* __restrict__ wout) {
    const int tid = threadIdx.x;
    if (blockIdx.x < MTOK) {
        const int row = blockIdx.x;
        const float4 xv = ((const float4*)(x + (size_t)row * DIM))[tid];
        float ss = xv.x*xv.x + xv.y*xv.y + xv.z*xv.z + xv.w*xv.w;
        #pragma unroll
        for (int off = 16; off > 0; off >>= 1)
            ss += __shfl_xor_sync(0xffffffffu, ss, off);
        __shared__ float wsum[8];
        const int lane = tid & 31, wid = tid >> 5;
        if (lane == 0) wsum[wid] = ss;
        __syncthreads();
        if (tid == 0) {
            float t = 0.f;
            #pragma unroll
            for (int i = 0; i < 8; ++i) t += wsum[i];
            wsum[0] = rsqrtf(t * (1.0f / DIM) + 1e-6f);
        }
        __syncthreads();
        const float scale = wsum[0];
        const float4 wv = ((const float4*)w)[tid];
        const int k0 = tid * 4;
        g_xnh[afrag_off(row, k0)]     = __floats2half2_rn(wv.x * (xv.x * scale), wv.y * (xv.y * scale));
        g_xnh[afrag_off(row, k0 + 2)] = __floats2half2_rn(wv.z * (xv.z * scale), wv.w * (xv.w * scale));
    } else {
        const int P1 = N1 * DIM / 2;
        const int P2 = DIM * DIM / 2;
        const int idx = (blockIdx.x - MTOK) * 256 + tid;
        if (idx < P1) {
            const int kh = idx & 1, lane = (idx >> 1) & 31, ks = (idx >> 6) & 1;
            const int nbkt = idx >> 7, nb = nbkt % 400, kt = nbkt / 400;
            const int gr = lane >> 2, tg = lane & 3;
            const int n = nb * 8 + gr;
            const int k = kt * 32 + ks * 16 + kh * 8 + tg * 2;
            float v0 = 0.f, v1 = 0.f;
            if (n < NQKV)              { v0 = wqkv[k * NQKV + n];        v1 = wqkv[(k+1) * NQKV + n]; }
            else if (n < NQKV + NGATE) { v0 = wgate[k * NGATE + n-NQKV]; v1 = wgate[(k+1) * NGATE + n-NQKV]; }
            g_w1h[idx] = __floats2half2_rn(v0, v1);
        } else if (idx < P1 + P2) {
            const int j = idx - P1;
            const int kh = j & 1, lane = (j >> 1) & 31, ks = (j >> 6) & 1;
            const int nbkt = j >> 7, nb = nbkt % 128, kt = nbkt / 128;
            const int gr = lane >> 2, tg = lane & 3;
            const int n = nb * 8 + gr;
            const int k = kt * 32 + ks * 16 + kh * 8 + tg * 2;
            g_w2h[j] = __floats2half2_rn(wout[k * DIM + n], wout[(k+1) * DIM + n]);
        }
    }
}

// ---- fp16 fragment-packed GEMM: 128x128x32 tiles, 4 warps of 64x64, 4-stage ----
template<int MODE>
__global__ void __launch_bounds__(128, 2) gemm_f16_kernel(
        const float* __restrict__ X, float* __restrict__ Out) {
    constexpr int KT = DIM / 32;
    constexpr int N = (MODE == 0) ? N1 : DIM;
    const __half2* __restrict__ Af = (MODE == 0) ? g_xnh : g_hfh;
    const __half2* __restrict__ Bf = (MODE == 0) ? g_w1h : g_w2h;

    extern __shared__ float smem[];
    const int tid = threadIdx.x;
    const int mb = blockIdx.y, n0 = blockIdx.x * 128;
    const int m0 = mb * 128;
    const uint32_t smem_base = smem_u32(smem);

    auto issue = [&](int kt) {
        if (kt < KT) {
            const uint32_t st = smem_base + (uint32_t)(kt & 3) * 16384u;
            const __half2* sA = Af + (size_t)(mb * 32 + kt) * 2048;
            const __half2* sB = Bf + ((size_t)kt * (N >> 3) + (n0 >> 3)) * 128;
            #pragma unroll
            for (int q = 0; q < 4; ++q)
                cp16(st + (uint32_t)(tid + q * 128) * 16u, sA + (tid + q * 128) * 4);
            #pragma unroll
            for (int q = 0; q < 4; ++q)
                cp16(st + 8192u + (uint32_t)(tid + q * 128) * 16u, sB + (tid + q * 128) * 4);
        }
        cp_commit();
    };

    float acc[4][8][4];
    #pragma unroll
    for (int i = 0; i < 4; ++i)
        #pragma unroll
        for (int j = 0; j < 8; ++j)
            #pragma unroll
            for (int q = 0; q < 4; ++q) acc[i][j][q] = 0.f;

    issue(0); issue(1); issue(2);

    const int lane = tid & 31, wid = tid >> 5;
    const int R0 = (wid >> 1) * 4;
    const int nb0 = (wid & 1) * 8;
    const int wm = R0 * 16, wn = nb0 * 8;
    const int gr = lane >> 2, tg = lane & 3;

    for (int kt = 0; kt < KT; ++kt) {
        cp_wait<2>();
        __syncthreads();
        issue(kt + 3);
        const __half2* As = (const __half2*)((const char*)smem + (kt & 3) * 16384);
        const __half2* Bs = As + 2048;
        #pragma unroll
        for (int ks = 0; ks < 2; ++ks) {
            float4 af[4]; float2 bf[8];
            #pragma unroll
            for (int i = 0; i < 4; ++i)
                af[i] = *(const float4*)(As + ((R0 + i) * 2 + ks) * 128 + lane * 4);
            #pragma unroll
            for (int j = 0; j < 8; ++j)
                bf[j] = *(const float2*)(Bs + ((nb0 + j) * 2 + ks) * 64 + lane * 2);
            #pragma unroll
            for (int i = 0; i < 4; ++i)
                #pragma unroll
                for (int j = 0; j < 8; ++j)
                    mma_f16(acc[i][j], FU(af[i].x), FU(af[i].y), FU(af[i].z), FU(af[i].w),
                            FU(bf[j].x), FU(bf[j].y));
        }
    }

    #pragma unroll
    for (int i = 0; i < 4; ++i) {
        #pragma unroll
        for (int j = 0; j < 8; ++j) {
            const int r0 = m0 + wm + i * 16 + gr;
            const int c0 = n0 + wn + j * 8 + tg * 2;
            if (MODE == 0) {
                if (c0 < NQKV) {
                    *(__half2*)(g_qkvh + (size_t)r0 * NQKV + c0) =
                        __floats2half2_rn(acc[i][j][0], acc[i][j][1]);
                    *(__half2*)(g_qkvh + (size_t)(r0 + 8) * NQKV + c0) =
                        __floats2half2_rn(acc[i][j][2], acc[i][j][3]);
                } else {
                    #pragma unroll
                    for (int q = 0; q < 4; ++q) {
                        const int r = r0 + (q >> 1) * 8;
                        const int c = c0 + (q & 1);
                        if (c < NQKV + NGATE) {
                            const int gl = c - NQKV;
                            float tt = tanhf(acc[i][j][q] * (1.0f / 15.0f));
                            g_gt[(size_t)gl * MTOK + r] =
                                1.0f / (1.0f + expf(-15.0f * tt));
                        }
                    }
                }
            } else {
                #pragma unroll
                for (int q = 0; q < 4; ++q) {
                    const int r = r0 + (q >> 1) * 8;
                    const int c = c0 + (q & 1);
                    Out[(size_t)r * DIM + c] = X[(size_t)r * DIM + c] + acc[i][j][q];
                }
            }
        }
    }
}

// ---- chunkwise phase 1: intra-chunk, fp16 m16n8k16 ----
#define SP 72     // half pitch
#define SP2 36    // half2 pitch
__global__ void __launch_bounds__(256) chunk_intra_kernel() {
    __shared__ __half Qh [64 * SP];   // (t,d); after GEMM1 reused as Ah (t,s)
    __shared__ __half Kh [64 * SP];   // (s,d)
    __shared__ __half Kth[64 * SP];   // (d,s) * Wc[s], col-swizzled
    __shared__ __half Vth[64 * SP];   // (e,s), col-swizzled
    __shared__ float LF[64], Wi[64], Wc[64];

    const int cidx = blockIdx.x;
    const int c = cidx & (NCHUNK - 1);
    const int bh = cidx >> 5;
    const int h = bh & 15, b = bh >> 4;
    const int m0 = b * SEQ + c * CHUNK;
    const int tid = threadIdx.x;

    float gi = 0.f, gf = 0.f;
    if (tid < 64) {
        gi = g_gt[(size_t)h * MTOK + m0 + tid];
        gf = g_gt[(size_t)(NH + h) * MTOK + m0 + tid];
    }
    uint4 hq[2], hk[2], hv[2];
    #pragma unroll
    for (int qq = 0; qq < 2; ++qq) {
        const int idx = tid + qq * 256;
        const int t = idx >> 3, d8 = (idx & 7) << 3;
        const __half* row = g_qkvh + (size_t)(m0 + t) * NQKV + h * 64 + d8;
        hq[qq] = *(const uint4*)row;
        hk[qq] = *(const uint4*)(row + 1024);
        hv[qq] = *(const uint4*)(row + 2048);
    }
    #pragma unroll
    for (int qq = 0; qq < 2; ++qq) {
        const int idx = tid + qq * 256;
        const int t = idx >> 3, d8 = (idx & 7) << 3;
        *(uint4*)(Qh + t * SP + d8) = hq[qq];
        *(uint4*)(Kh + t * SP + d8) = hk[qq];
        const __half* pv = (const __half*)&hv[qq];
        #pragma unroll
        for (int jj = 0; jj < 8; ++jj) {
            const int d = d8 + jj;
            Vth[d * SP + (t ^ (((d >> 2) & 15) << 1))] = pv[jj];
        }
    }
    if (tid < 64) { Wi[tid] = gi; LF[tid] = __logf(gf); }
    __syncthreads();

    if (tid < 32) {
        float x0 = LF[tid], x1 = LF[tid + 32];
        #pragma unroll
        for (int off = 1; off < 32; off <<= 1) {
            float y = __shfl_up_sync(0xffffffffu, x0, off);
            if (tid >= off) x0 += y;
        }
        const float tot = __shfl_sync(0xffffffffu, x0, 31);
        #pragma unroll
        for (int off = 1; off < 32; off <<= 1) {
            float y = __shfl_up_sync(0xffffffffu, x1, off);
            if (tid >= off) x1 += y;
        }
        x1 += tot;
        LF[tid] = x0; LF[tid + 32] = x1;
        g_el[(size_t)h * MTOK + m0 + tid]      = __expf(x0);
        g_el[(size_t)h * MTOK + m0 + tid + 32] = __expf(x1);
    }
    __syncthreads();
    if (tid < 64) Wc[tid] = __expf(LF[63] - LF[tid]) * Wi[tid];
    if (tid == 0) g_Fc[cidx] = __expf(LF[63]);
    __syncthreads();

    #pragma unroll
    for (int qq = 0; qq < 2; ++qq) {
        const int idx = tid + qq * 256;
        const int t = idx >> 3, d8 = (idx & 7) << 3;
        const float wcs = Wc[t];
        const __half* pk = (const __half*)&hk[qq];
        #pragma unroll
        for (int jj = 0; jj < 8; ++jj) {
            const int d = d8 + jj;
            Kth[d * SP + (t ^ (((d >> 2) & 15) << 1))] =
                __float2half(wcs * __half2float(pk[jj]));
        }
    }
    __syncthreads();

    const int lane = tid & 31, wid = tid >> 5;
    const int gr = lane >> 2, tg = lane & 3;
    const int wm = (wid >> 1) * 16, wn = (wid & 1) * 32;
    const int ra = wm + gr, rb = wm + 8 + gr;

    float acc1[4][4];
    #pragma unroll
    for (int j = 0; j < 4; ++j)
        #pragma unroll
        for (int q = 0; q < 4; ++q) acc1[j][q] = 0.f;
    {
        const __half2* Q2 = (const __half2*)Qh;
        const __half2* K2 = (const __half2*)Kh;
        #pragma unroll
        for (int ks = 0; ks < 4; ++ks) {
            const int kh2 = ks * 8 + tg;
            uint32_t a0 = H2U(Q2[ra * SP2 + kh2]);
            uint32_t a1 = H2U(Q2[rb * SP2 + kh2]);
            uint32_t a2 = H2U(Q2[ra * SP2 + kh2 + 4]);
            uint32_t a3 = H2U(Q2[rb * SP2 + kh2 + 4]);
            #pragma unroll
            for (int j = 0; j < 4; ++j) {
                const int n = wn + j * 8 + gr;
                mma_f16(acc1[j], a0, a1, a2, a3,
                        H2U(K2[n * SP2 + kh2]), H2U(K2[n * SP2 + kh2 + 4]));
            }
        }
    }
    __syncthreads();

    {
        __half* Ah = Qh;
        #pragma unroll
        for (int j = 0; j < 4; ++j)
            #pragma unroll
            for (int q = 0; q < 4; ++q) {
                const int t = wm + gr + (q >> 1) * 8;
                const int s = wn + j * 8 + tg * 2 + (q & 1);
                float v = 0.f;
                if (s <= t) v = acc1[j][q] * __expf(LF[t] - LF[s]) * Wi[s];
                Ah[t * SP + s] = __float2half(v);
            }
    }
    __syncthreads();

    float hacc[4][4], uacc[4][4];
    #pragma unroll
    for (int j = 0; j < 4; ++j)
        #pragma unroll
        for (int q = 0; q < 4; ++q) { hacc[j][q] = 0.f; uacc[j][q] = 0.f; }
    {
        const __half2* A2  = (const __half2*)Qh;
        const __half2* Kt2 = (const __half2*)Kth;
        const __half2* Vt2 = (const __half2*)Vth;
        const int swa = (ra >> 2) & 15, swb = (rb >> 2) & 15;
        #pragma unroll
        for (int ks = 0; ks < 4; ++ks) {
            const int kh2 = ks * 8 + tg;
            uint32_t ha0 = H2U(A2[ra * SP2 + kh2]);
            uint32_t ha1 = H2U(A2[rb * SP2 + kh2]);
            uint32_t ha2 = H2U(A2[ra * SP2 + kh2 + 4]);
            uint32_t ha3 = H2U(A2[rb * SP2 + kh2 + 4]);
            uint32_t ua0 = H2U(Kt2[ra * SP2 + (kh2 ^ swa)]);
            uint32_t ua1 = H2U(Kt2[rb * SP2 + (kh2 ^ swb)]);
            uint32_t ua2 = H2U(Kt2[ra * SP2 + ((kh2 + 4) ^ swa)]);
            uint32_t ua3 = H2U(Kt2[rb * SP2 + ((kh2 + 4) ^ swb)]);
            #pragma unroll
            for (int j = 0; j < 4; ++j) {
                const int n = wn + j * 8 + gr;
                const int swn = (n >> 2) & 15;
                uint32_t b0 = H2U(Vt2[n * SP2 + (kh2 ^ swn)]);
                uint32_t b1 = H2U(Vt2[n * SP2 + ((kh2 + 4) ^ swn)]);
                mma_f16(hacc[j], ha0, ha1, ha2, ha3, b0, b1);
                mma_f16(uacc[j], ua0, ua1, ua2, ua3, b0, b1);
            }
        }
    }
    #pragma unroll
    for (int j = 0; j < 4; ++j)
        #pragma unroll
        for (int qp = 0; qp < 2; ++qp) {
            const int row = wm + gr + qp * 8;
            const int col = wn + j * 8 + tg * 2;
            *(__half2*)(g_hh + (size_t)(m0 + row) * DIM + h * 64 + col) =
                __floats2half2_rn(hacc[j][qp*2], hacc[j][qp*2+1]);
            *(__half2*)(g_Uh + (size_t)cidx * 4096 + row * 64 + col) =
                __floats2half2_rn(uacc[j][qp*2], uacc[j][qp*2+1]);
        }
}

// ---- phase 2a: element-parallel state prefix (4 elems/thread, 65536 threads) ----
__global__ void __launch_bounds__(256) state_prefix_kernel(const float* __restrict__ hidden) {
    const int gid = blockIdx.x * 256 + threadIdx.x;   // 65536 threads
    const int bh = gid >> 10;
    const int off = (gid & 1023) * 4;
    float S[4];
    {
        const float4 h0 = *(const float4*)(hidden + (size_t)bh * 4096 + off);
        S[0]=h0.x; S[1]=h0.y; S[2]=h0.z; S[3]=h0.w;
    }
    const float* fc = g_Fc + bh * NCHUNK;
    #pragma unroll 8
    for (int c = 0; c < NCHUNK; ++c) {
        const size_t p = (size_t)(bh * NCHUNK + c) * 4096 + off;
        uint2 so;
        __half2* ph = (__half2*)&so;
        ph[0] = __floats2half2_rn(S[0], S[1]);
        ph[1] = __floats2half2_rn(S[2], S[3]);
        *(uint2*)(g_Sh + p) = so;
        const uint2 uu = *(const uint2*)(g_Uh + p);
        const __half2* pu = (const __half2*)&uu;
        const float F = fc[c];
        const float2 u0 = __half22float2(pu[0]);
        const float2 u1 = __half22float2(pu[1]);
        S[0] = F * S[0] + u0.x;
        S[1] = F * S[1] + u0.y;
        S[2] = F * S[2] + u1.x;
        S[3] = F * S[3] + u1.y;
    }
}

// ---- phase 2b: h = (exp(LF)*q @ S_c + h_intra) * o, fp16 m16n8k16 ----
__global__ void __launch_bounds__(256) chunk_inter_kernel() {
    __shared__ __half Qsh[64 * SP];   // (t,d) = exp(LF_t) * q
    __shared__ __half Sth[64 * SP];   // (e,d) transposed S, col-swizzled
    __shared__ float Og[64], Eb[64];

    const int cidx = blockIdx.x;
    const int c = cidx & (NCHUNK - 1);
    const int bh = cidx >> 5;
    const int h = bh & 15, b = bh >> 4;
    const int m0 = b * SEQ + c * CHUNK;
    const int tid = threadIdx.x;

    uint4 hq[2], hs[2];
    #pragma unroll
    for (int qq = 0; qq < 2; ++qq) {
        const int idx = tid + qq * 256;
        const int t = idx >> 3, d8 = (idx & 7) << 3;
        hq[qq] = *(const uint4*)(g_qkvh + (size_t)(m0 + t) * NQKV + h * 64 + d8);
        hs[qq] = *(const uint4*)(g_Sh + (size_t)cidx * 4096 + t * 64 + d8);
    }
    if (tid < 64) {
        Og[tid] = g_gt[(size_t)(2 * NH + h) * MTOK + m0 + tid];
        Eb[tid] = g_el[(size_t)h * MTOK + m0 + tid];
    }
    __syncthreads();

    #pragma unroll
    for (int qq = 0; qq < 2; ++qq) {
        const int idx = tid + qq * 256;
        const int t = idx >> 3, d8 = (idx & 7) << 3;
        {
            const float e = Eb[t];
            const __half2* pq = (const __half2*)&hq[qq];
            __half2* dst = (__half2*)(Qsh + t * SP + d8);
            #pragma unroll
            for (int jj = 0; jj < 4; ++jj) {
                float2 f = __half22float2(pq[jj]);
                dst[jj] = __floats2half2_rn(f.x * e, f.y * e);
            }
        }
        {
            const int d = t;
            const __half* ps = (const __half*)&hs[qq];
            #pragma unroll
            for (int jj = 0; jj < 8; ++jj) {
                const int e = d8 + jj;
                Sth[e * SP + (d ^ (((e >> 2) & 15) << 1))] = ps[jj];
            }
        }
    }
    __syncthreads();

    const int lane = tid & 31, wid = tid >> 5;
    const int gr = lane >> 2, tg = lane & 3;
    const int wm = (wid >> 1) * 16, wn = (wid & 1) * 32;
    const int ra = wm + gr, rb = wm + 8 + gr;

    float acc[4][4];
    #pragma unroll
    for (int j = 0; j < 4; ++j)
        #pragma unroll
        for (int q = 0; q < 4; ++q) acc[j][q] = 0.f;
    {
        const __half2* Q2 = (const __half2*)Qsh;
        const __half2* St2 = (const __half2*)Sth;
        #pragma unroll
        for (int ks = 0; ks < 4; ++ks) {
            const int kh2 = ks * 8 + tg;
            uint32_t a0 = H2U(Q2[ra * SP2 + kh2]);
            uint32_t a1 = H2U(Q2[rb * SP2 + kh2]);
            uint32_t a2 = H2U(Q2[ra * SP2 + kh2 + 4]);
            uint32_t a3 = H2U(Q2[rb * SP2 + kh2 + 4]);
            #pragma unroll
            for (int j = 0; j < 4; ++j) {
                const int n = wn + j * 8 + gr;
                const int swn = (n >> 2) & 15;
                mma_f16(acc[j], a0, a1, a2, a3,
                        H2U(St2[n * SP2 + (kh2 ^ swn)]),
                        H2U(St2[n * SP2 + ((kh2 + 4) ^ swn)]));
            }
        }
    }

    #pragma unroll
    for (int j = 0; j < 4; ++j)
        #pragma unroll
        for (int qp = 0; qp < 2; ++qp) {
            const int row = wm + gr + qp * 8;
            const int col = wn + j * 8 + tg * 2;
            const int m = m0 + row;
            const float og = Og[row];
            const float2 hi = __half22float2(
                *(const __half2*)(g_hh + (size_t)m * DIM + h * 64 + col));
            const float hv0 = (acc[j][qp*2]   + hi.x) * og;
            const float hv1 = (acc[j][qp*2+1] + hi.y) * og;
            g_hfh[afrag_off(m, h * 64 + col)] = __floats2half2_rn(hv0, hv1);
        }
}

extern "C" void kernel_launch(void* const* d_in, const int* in_sizes, int n_in,
                              void* d_out, int out_size) {
    const float* x      = (const float*)d_in[0];
    const float* hidden = (const float*)d_in[1];
    const float* w_rms  = (const float*)d_in[2];
    const float* w_qkv  = (const float*)d_in[3];
    const float* w_gate = (const float*)d_in[4];
    const float* w_out  = (const float*)d_in[5];
    float* out = (float*)d_out;

    static bool attr_done = false;
    if (!attr_done) {
        cudaFuncSetAttribute(gemm_f16_kernel<0>,
            cudaFuncAttributeMaxDynamicSharedMemorySize, 65536);
        cudaFuncSetAttribute(gemm_f16_kernel<1>,
            cudaFuncAttributeMaxDynamicSharedMemorySize, 65536);
        attr_done = true;
    }

    startup_kernel<<<MTOK + PREP_BLOCKS, 256>>>(x, w_rms, w_qkv, w_gate, w_out);
    {
        dim3 grid(N1 / 128, MTOK / 128);
        gemm_f16_kernel<0><<<grid, 128, 65536>>>(nullptr, nullptr);
    }
    chunk_intra_kernel<<<TOTCHUNK, 256>>>();
    state_prefix_kernel<<<256, 256>>>(hidden);
    chunk_inter_kernel<<<TOTCHUNK, 256>>>();
    {
        dim3 grid(DIM / 128, MTOK / 128);
        gemm_f16_kernel<1><<<grid, 128, 65536>>>(x, out);
    }
}

// round 17
// speedup vs baseline: 1.0344x; 1.0137x over previous
#include <cuda_runtime.h>
#include <cuda_fp16.h>
#include <cstdint>
#include <cmath>

#define BATCH 4
#define SEQ   2048
#define DIM   1024
#define NH    16
#define DH    64
#define MTOK  (BATCH*SEQ)
#define N1    3200
#define NQKV  3072
#define NGATE 48
#define CHUNK 64
#define NCHUNK (SEQ/CHUNK)              // 32
#define TOTCHUNK (BATCH*NH*NCHUNK)      // 2048
#define PREP_BLOCKS 8448                // (N1*DIM/2 + DIM*DIM/2) / 256

// fp16 fragment-packed GEMM operands
__device__ __half2 g_xnh [MTOK * DIM / 2];    // A-fragments of rmsnormed x
__device__ __half2 g_w1h [N1 * DIM / 2];      // B-fragments of [wqkv|wgate|0]
__device__ __half2 g_w2h [DIM * DIM / 2];     // B-fragments of w_out
__device__ __half2 g_hfh [MTOK * DIM / 2];    // A-fragments of final h
// plain buffers
__device__ __half g_qkvh[MTOK * NQKV];        // qkv in fp16, [m][3072]
__device__ float  g_gt  [3 * NH * MTOK];      // gates transposed [gate][h][m]
__device__ float  g_el  [NH * MTOK];          // exp(LF_t), [h][m]
__device__ __half g_hh  [MTOK * DIM];         // h_intra (fp16)
__device__ __half g_Uh  [TOTCHUNK * 64 * 64]; // chunk increments (fp16)
__device__ __half g_Sh  [TOTCHUNK * 64 * 64]; // state before each chunk (fp16)
__device__ float  g_Fc  [TOTCHUNK];

__device__ __forceinline__ uint32_t smem_u32(const void* p) {
    return (uint32_t)__cvta_generic_to_shared(p);
}
__device__ __forceinline__ void cp16(uint32_t s, const void* g) {
    asm volatile("cp.async.cg.shared.global [%0], [%1], 16;\n" :: "r"(s), "l"(g));
}
__device__ __forceinline__ void cp_commit() {
    asm volatile("cp.async.commit_group;\n" ::: "memory");
}
template<int N> __device__ __forceinline__ void cp_wait() {
    asm volatile("cp.async.wait_group %0;\n" :: "n"(N) : "memory");
}
__device__ __forceinline__ void mma_f16(float c[4],
        uint32_t a0, uint32_t a1, uint32_t a2, uint32_t a3,
        uint32_t b0, uint32_t b1) {
    asm volatile(
        "mma.sync.aligned.m16n8k16.row.col.f32.f16.f16.f32 "
        "{%0,%1,%2,%3},{%4,%5,%6,%7},{%8,%9},{%0,%1,%2,%3};\n"
        : "+f"(c[0]), "+f"(c[1]), "+f"(c[2]), "+f"(c[3])
        : "r"(a0), "r"(a1), "r"(a2), "r"(a3), "r"(b0), "r"(b1));
}
#define FU(x) __float_as_uint(x)
__device__ __forceinline__ uint32_t H2U(__half2 v) { return *(uint32_t*)&v; }

// A-fragment half2 offset for (m, k even)
__device__ __forceinline__ size_t afrag_off(int m, int k) {
    const int mb = m >> 7, kt = k >> 5, R = (m >> 4) & 7, ks = (k >> 4) & 1;
    const int gr = m & 7, hb = (m >> 3) & 1, tg = (k & 7) >> 1, kh = (k >> 3) & 1;
    return ((((size_t)(mb * 32 + kt) * 8 + R) * 2 + ks) * 128)
         + (gr * 4 + tg) * 4 + (hb + 2 * kh);
}

// ---- fused startup: rmsnorm (blocks 0..MTOK-1) + weight prep (rest) ----
__global__ void __launch_bounds__(256) startup_kernel(
        const float* __restrict__ x, const float* __restrict__ w,
        const float* __restrict__ wqkv, const float* __restrict__ wgate,
        const float* __restrict__ wout) {
    const int tid = threadIdx.x;
    if (blockIdx.x < MTOK) {
        const int row = blockIdx.x;
        const float4 xv = ((const float4*)(x + (size_t)row * DIM))[tid];
        float ss = xv.x*xv.x + xv.y*xv.y + xv.z*xv.z + xv.w*xv.w;
        #pragma unroll
        for (int off = 16; off > 0; off >>= 1)
            ss += __shfl_xor_sync(0xffffffffu, ss, off);
        __shared__ float wsum[8];
        const int lane = tid & 31, wid = tid >> 5;
        if (lane == 0) wsum[wid] = ss;
        __syncthreads();
        if (tid == 0) {
            float t = 0.f;
            #pragma unroll
            for (int i = 0; i < 8; ++i) t += wsum[i];
            wsum[0] = rsqrtf(t * (1.0f / DIM) + 1e-6f);
        }
        __syncthreads();
        const float scale = wsum[0];
        const float4 wv = ((const float4*)w)[tid];
        const int k0 = tid * 4;
        g_xnh[afrag_off(row, k0)]     = __floats2half2_rn(wv.x * (xv.x * scale), wv.y * (xv.y * scale));
        g_xnh[afrag_off(row, k0 + 2)] = __floats2half2_rn(wv.z * (xv.z * scale), wv.w * (xv.w * scale));
    } else {
        const int P1 = N1 * DIM / 2;
        const int P2 = DIM * DIM / 2;
        const int idx = (blockIdx.x - MTOK) * 256 + tid;
        if (idx < P1) {
            const int kh = idx & 1, lane = (idx >> 1) & 31, ks = (idx >> 6) & 1;
            const int nbkt = idx >> 7, nb = nbkt % 400, kt = nbkt / 400;
            const int gr = lane >> 2, tg = lane & 3;
            const int n = nb * 8 + gr;
            const int k = kt * 32 + ks * 16 + kh * 8 + tg * 2;
            float v0 = 0.f, v1 = 0.f;
            if (n < NQKV)              { v0 = wqkv[k * NQKV + n];        v1 = wqkv[(k+1) * NQKV + n]; }
            else if (n < NQKV + NGATE) { v0 = wgate[k * NGATE + n-NQKV]; v1 = wgate[(k+1) * NGATE + n-NQKV]; }
            g_w1h[idx] = __floats2half2_rn(v0, v1);
        } else if (idx < P1 + P2) {
            const int j = idx - P1;
            const int kh = j & 1, lane = (j >> 1) & 31, ks = (j >> 6) & 1;
            const int nbkt = j >> 7, nb = nbkt % 128, kt = nbkt / 128;
            const int gr = lane >> 2, tg = lane & 3;
            const int n = nb * 8 + gr;
            const int k = kt * 32 + ks * 16 + kh * 8 + tg * 2;
            g_w2h[j] = __floats2half2_rn(wout[k * DIM + n], wout[(k+1) * DIM + n]);
        }
    }
}

// ---- fp16 fragment-packed GEMM: 128x128x32 tiles, 4 warps of 64x64, 4-stage ----
template<int MODE>
__global__ void __launch_bounds__(128, 2) gemm_f16_kernel(
        const float* __restrict__ X, float* __restrict__ Out) {
    constexpr int KT = DIM / 32;
    constexpr int N = (MODE == 0) ? N1 : DIM;
    const __half2* __restrict__ Af = (MODE == 0) ? g_xnh : g_hfh;
    const __half2* __restrict__ Bf = (MODE == 0) ? g_w1h : g_w2h;

    extern __shared__ float smem[];
    const int tid = threadIdx.x;
    const int mb = blockIdx.y, n0 = blockIdx.x * 128;
    const int m0 = mb * 128;
    const uint32_t smem_base = smem_u32(smem);

    auto issue = [&](int kt) {
        if (kt < KT) {
            const uint32_t st = smem_base + (uint32_t)(kt & 3) * 16384u;
            const __half2* sA = Af + (size_t)(mb * 32 + kt) * 2048;
            const __half2* sB = Bf + ((size_t)kt * (N >> 3) + (n0 >> 3)) * 128;
            #pragma unroll
            for (int q = 0; q < 4; ++q)
                cp16(st + (uint32_t)(tid + q * 128) * 16u, sA + (tid + q * 128) * 4);
            #pragma unroll
            for (int q = 0; q < 4; ++q)
                cp16(st + 8192u + (uint32_t)(tid + q * 128) * 16u, sB + (tid + q * 128) * 4);
        }
        cp_commit();
    };

    float acc[4][8][4];
    #pragma unroll
    for (int i = 0; i < 4; ++i)
        #pragma unroll
        for (int j = 0; j < 8; ++j)
            #pragma unroll
            for (int q = 0; q < 4; ++q) acc[i][j][q] = 0.f;

    issue(0); issue(1); issue(2);

    const int lane = tid & 31, wid = tid >> 5;
    const int R0 = (wid >> 1) * 4;
    const int nb0 = (wid & 1) * 8;
    const int wm = R0 * 16, wn = nb0 * 8;
    const int gr = lane >> 2, tg = lane & 3;

    for (int kt = 0; kt < KT; ++kt) {
        cp_wait<2>();
        __syncthreads();
        issue(kt + 3);
        const __half2* As = (const __half2*)((const char*)smem + (kt & 3) * 16384);
        const __half2* Bs = As + 2048;
        #pragma unroll
        for (int ks = 0; ks < 2; ++ks) {
            float4 af[4]; float2 bf[8];
            #pragma unroll
            for (int i = 0; i < 4; ++i)
                af[i] = *(const float4*)(As + ((R0 + i) * 2 + ks) * 128 + lane * 4);
            #pragma unroll
            for (int j = 0; j < 8; ++j)
                bf[j] = *(const float2*)(Bs + ((nb0 + j) * 2 + ks) * 64 + lane * 2);
            #pragma unroll
            for (int i = 0; i < 4; ++i)
                #pragma unroll
                for (int j = 0; j < 8; ++j)
                    mma_f16(acc[i][j], FU(af[i].x), FU(af[i].y), FU(af[i].z), FU(af[i].w),
                            FU(bf[j].x), FU(bf[j].y));
        }
    }

    #pragma unroll
    for (int i = 0; i < 4; ++i) {
        #pragma unroll
        for (int j = 0; j < 8; ++j) {
            const int r0 = m0 + wm + i * 16 + gr;
            const int c0 = n0 + wn + j * 8 + tg * 2;
            if (MODE == 0) {
                if (c0 < NQKV) {
                    *(__half2*)(g_qkvh + (size_t)r0 * NQKV + c0) =
                        __floats2half2_rn(acc[i][j][0], acc[i][j][1]);
                    *(__half2*)(g_qkvh + (size_t)(r0 + 8) * NQKV + c0) =
                        __floats2half2_rn(acc[i][j][2], acc[i][j][3]);
                } else {
                    #pragma unroll
                    for (int q = 0; q < 4; ++q) {
                        const int r = r0 + (q >> 1) * 8;
                        const int c = c0 + (q & 1);
                        if (c < NQKV + NGATE) {
                            const int gl = c - NQKV;
                            float tt = tanhf(acc[i][j][q] * (1.0f / 15.0f));
                            g_gt[(size_t)gl * MTOK + r] =
                                1.0f / (1.0f + expf(-15.0f * tt));
                        }
                    }
                }
            } else {
                #pragma unroll
                for (int q = 0; q < 4; ++q) {
                    const int r = r0 + (q >> 1) * 8;
                    const int c = c0 + (q & 1);
                    Out[(size_t)r * DIM + c] = X[(size_t)r * DIM + c] + acc[i][j][q];
                }
            }
        }
    }
}

// ---- chunkwise phase 1: intra-chunk, fp16 m16n8k16 ----
#define SP 72     // half pitch
#define SP2 36    // half2 pitch
__global__ void __launch_bounds__(256) chunk_intra_kernel() {
    __shared__ __half Qh [64 * SP];   // (t,d); after GEMM1 reused as Ah (t,s)
    __shared__ __half Kh [64 * SP];   // (s,d)
    __shared__ __half Kth[64 * SP];   // (d,s) * Wc[s], col-swizzled
    __shared__ __half Vth[64 * SP];   // (e,s), col-swizzled
    __shared__ float LF[64], Wi[64], Wc[64];

    const int cidx = blockIdx.x;
    const int c = cidx & (NCHUNK - 1);
    const int bh = cidx >> 5;
    const int h = bh & 15, b = bh >> 4;
    const int m0 = b * SEQ + c * CHUNK;
    const int tid = threadIdx.x;

    float gi = 0.f, gf = 0.f;
    if (tid < 64) {
        gi = g_gt[(size_t)h * MTOK + m0 + tid];
        gf = g_gt[(size_t)(NH + h) * MTOK + m0 + tid];
    }
    uint4 hq[2], hk[2], hv[2];
    #pragma unroll
    for (int qq = 0; qq < 2; ++qq) {
        const int idx = tid + qq * 256;
        const int t = idx >> 3, d8 = (idx & 7) << 3;
        const __half* row = g_qkvh + (size_t)(m0 + t) * NQKV + h * 64 + d8;
        hq[qq] = *(const uint4*)row;
        hk[qq] = *(const uint4*)(row + 1024);
        hv[qq] = *(const uint4*)(row + 2048);
    }
    #pragma unroll
    for (int qq = 0; qq < 2; ++qq) {
        const int idx = tid + qq * 256;
        const int t = idx >> 3, d8 = (idx & 7) << 3;
        *(uint4*)(Qh + t * SP + d8) = hq[qq];
        *(uint4*)(Kh + t * SP + d8) = hk[qq];
        const __half* pv = (const __half*)&hv[qq];
        #pragma unroll
        for (int jj = 0; jj < 8; ++jj) {
            const int d = d8 + jj;
            Vth[d * SP + (t ^ (((d >> 2) & 15) << 1))] = pv[jj];
        }
    }
    if (tid < 64) { Wi[tid] = gi; LF[tid] = __logf(gf); }
    __syncthreads();

    if (tid < 32) {
        float x0 = LF[tid], x1 = LF[tid + 32];
        #pragma unroll
        for (int off = 1; off < 32; off <<= 1) {
            float y = __shfl_up_sync(0xffffffffu, x0, off);
            if (tid >= off) x0 += y;
        }
        const float tot = __shfl_sync(0xffffffffu, x0, 31);
        #pragma unroll
        for (int off = 1; off < 32; off <<= 1) {
            float y = __shfl_up_sync(0xffffffffu, x1, off);
            if (tid >= off) x1 += y;
        }
        x1 += tot;
        LF[tid] = x0; LF[tid + 32] = x1;
        g_el[(size_t)h * MTOK + m0 + tid]      = __expf(x0);
        g_el[(size_t)h * MTOK + m0 + tid + 32] = __expf(x1);
    }
    __syncthreads();
    if (tid < 64) Wc[tid] = __expf(LF[63] - LF[tid]) * Wi[tid];
    if (tid == 0) g_Fc[cidx] = __expf(LF[63]);
    __syncthreads();

    #pragma unroll
    for (int qq = 0; qq < 2; ++qq) {
        const int idx = tid + qq * 256;
        const int t = idx >> 3, d8 = (idx & 7) << 3;
        const float wcs = Wc[t];
        const __half* pk = (const __half*)&hk[qq];
        #pragma unroll
        for (int jj = 0; jj < 8; ++jj) {
            const int d = d8 + jj;
            Kth[d * SP + (t ^ (((d >> 2) & 15) << 1))] =
                __float2half(wcs * __half2float(pk[jj]));
        }
    }
    __syncthreads();

    const int lane = tid & 31, wid = tid >> 5;
    const int gr = lane >> 2, tg = lane & 3;
    const int wm = (wid >> 1) * 16, wn = (wid & 1) * 32;
    const int ra = wm + gr, rb = wm + 8 + gr;

    float acc1[4][4];
    #pragma unroll
    for (int j = 0; j < 4; ++j)
        #pragma unroll
        for (int q = 0; q < 4; ++q) acc1[j][q] = 0.f;
    {
        const __half2* Q2 = (const __half2*)Qh;
        const __half2* K2 = (const __half2*)Kh;
        #pragma unroll
        for (int ks = 0; ks < 4; ++ks) {
            const int kh2 = ks * 8 + tg;
            uint32_t a0 = H2U(Q2[ra * SP2 + kh2]);
            uint32_t a1 = H2U(Q2[rb * SP2 + kh2]);
            uint32_t a2 = H2U(Q2[ra * SP2 + kh2 + 4]);
            uint32_t a3 = H2U(Q2[rb * SP2 + kh2 + 4]);
            #pragma unroll
            for (int j = 0; j < 4; ++j) {
                const int n = wn + j * 8 + gr;
                mma_f16(acc1[j], a0, a1, a2, a3,
                        H2U(K2[n * SP2 + kh2]), H2U(K2[n * SP2 + kh2 + 4]));
            }
        }
    }
    __syncthreads();

    {
        __half* Ah = Qh;
        #pragma unroll
        for (int j = 0; j < 4; ++j)
            #pragma unroll
            for (int q = 0; q < 4; ++q) {
                const int t = wm + gr + (q >> 1) * 8;
                const int s = wn + j * 8 + tg * 2 + (q & 1);
                float v = 0.f;
                if (s <= t) v = acc1[j][q] * __expf(LF[t] - LF[s]) * Wi[s];
                Ah[t * SP + s] = __float2half(v);
            }
    }
    __syncthreads();

    float hacc[4][4], uacc[4][4];
    #pragma unroll
    for (int j = 0; j < 4; ++j)
        #pragma unroll
        for (int q = 0; q < 4; ++q) { hacc[j][q] = 0.f; uacc[j][q] = 0.f; }
    {
        const __half2* A2  = (const __half2*)Qh;
        const __half2* Kt2 = (const __half2*)Kth;
        const __half2* Vt2 = (const __half2*)Vth;
        const int swa = (ra >> 2) & 15, swb = (rb >> 2) & 15;
        #pragma unroll
        for (int ks = 0; ks < 4; ++ks) {
            const int kh2 = ks * 8 + tg;
            uint32_t ha0 = H2U(A2[ra * SP2 + kh2]);
            uint32_t ha1 = H2U(A2[rb * SP2 + kh2]);
            uint32_t ha2 = H2U(A2[ra * SP2 + kh2 + 4]);
            uint32_t ha3 = H2U(A2[rb * SP2 + kh2 + 4]);
            uint32_t ua0 = H2U(Kt2[ra * SP2 + (kh2 ^ swa)]);
            uint32_t ua1 = H2U(Kt2[rb * SP2 + (kh2 ^ swb)]);
            uint32_t ua2 = H2U(Kt2[ra * SP2 + ((kh2 + 4) ^ swa)]);
            uint32_t ua3 = H2U(Kt2[rb * SP2 + ((kh2 + 4) ^ swb)]);
            #pragma unroll
            for (int j = 0; j < 4; ++j) {
                const int n = wn + j * 8 + gr;
                const int swn = (n >> 2) & 15;
                uint32_t b0 = H2U(Vt2[n * SP2 + (kh2 ^ swn)]);
                uint32_t b1 = H2U(Vt2[n * SP2 + ((kh2 + 4) ^ swn)]);
                mma_f16(hacc[j], ha0, ha1, ha2, ha3, b0, b1);
                mma_f16(uacc[j], ua0, ua1, ua2, ua3, b0, b1);
            }
        }
    }
    #pragma unroll
    for (int j = 0; j < 4; ++j)
        #pragma unroll
        for (int qp = 0; qp < 2; ++qp) {
            const int row = wm + gr + qp * 8;
            const int col = wn + j * 8 + tg * 2;
            *(__half2*)(g_hh + (size_t)(m0 + row) * DIM + h * 64 + col) =
                __floats2half2_rn(hacc[j][qp*2], hacc[j][qp*2+1]);
            *(__half2*)(g_Uh + (size_t)cidx * 4096 + row * 64 + col) =
                __floats2half2_rn(uacc[j][qp*2], uacc[j][qp*2+1]);
        }
}

// ---- phase 2a: state prefix, depth-2 software-pipelined U loads ----
__global__ void __launch_bounds__(256) state_prefix_kernel(const float* __restrict__ hidden) {
    const int gid = blockIdx.x * 256 + threadIdx.x;   // 65536 threads
    const int bh = gid >> 10;
    const int off = (gid & 1023) * 4;
    float S[4];
    {
        const float4 h0 = *(const float4*)(hidden + (size_t)bh * 4096 + off);
        S[0]=h0.x; S[1]=h0.y; S[2]=h0.z; S[3]=h0.w;
    }
    const float* fc = g_Fc + bh * NCHUNK;
    const __half* Ub = g_Uh + (size_t)bh * NCHUNK * 4096 + off;
    __half* Sb = g_Sh + (size_t)bh * NCHUNK * 4096 + off;

    uint2 ubuf[2];
    ubuf[0] = *(const uint2*)(Ub);
    ubuf[1] = *(const uint2*)(Ub + 4096);
    #pragma unroll 8
    for (int c = 0; c < NCHUNK; ++c) {
        // store S_c first (independent of U_c)
        uint2 so;
        __half2* ph = (__half2*)&so;
        ph[0] = __floats2half2_rn(S[0], S[1]);
        ph[1] = __floats2half2_rn(S[2], S[3]);
        *(uint2*)(Sb + (size_t)c * 4096) = so;
        const uint2 u_cur = ubuf[c & 1];
        if (c + 2 < NCHUNK)
            ubuf[c & 1] = *(const uint2*)(Ub + (size_t)(c + 2) * 4096);
        const __half2* pu = (const __half2*)&u_cur;
        const float F = fc[c];
        const float2 u0 = __half22float2(pu[0]);
        const float2 u1 = __half22float2(pu[1]);
        S[0] = F * S[0] + u0.x;
        S[1] = F * S[1] + u0.y;
        S[2] = F * S[2] + u1.x;
        S[3] = F * S[3] + u1.y;
    }
}

// ---- phase 2b: h = (exp(LF)*q @ S_c + h_intra) * o, fp16 m16n8k16 ----
__global__ void __launch_bounds__(256) chunk_inter_kernel() {
    __shared__ __half Qsh[64 * SP];   // (t,d) = exp(LF_t) * q
    __shared__ __half Sth[64 * SP];   // (e,d) transposed S, col-swizzled
    __shared__ float Og[64], Eb[64];

    const int cidx = blockIdx.x;
    const int c = cidx & (NCHUNK - 1);
    const int bh = cidx >> 5;
    const int h = bh & 15, b = bh >> 4;
    const int m0 = b * SEQ + c * CHUNK;
    const int tid = threadIdx.x;

    uint4 hq[2], hs[2];
    #pragma unroll
    for (int qq = 0; qq < 2; ++qq) {
        const int idx = tid + qq * 256;
        const int t = idx >> 3, d8 = (idx & 7) << 3;
        hq[qq] = *(const uint4*)(g_qkvh + (size_t)(m0 + t) * NQKV + h * 64 + d8);
        hs[qq] = *(const uint4*)(g_Sh + (size_t)cidx * 4096 + t * 64 + d8);
    }
    if (tid < 64) {
        Og[tid] = g_gt[(size_t)(2 * NH + h) * MTOK + m0 + tid];
        Eb[tid] = g_el[(size_t)h * MTOK + m0 + tid];
    }
    __syncthreads();

    #pragma unroll
    for (int qq = 0; qq < 2; ++qq) {
        const int idx = tid + qq * 256;
        const int t = idx >> 3, d8 = (idx & 7) << 3;
        {
            const float e = Eb[t];
            const __half2* pq = (const __half2*)&hq[qq];
            __half2* dst = (__half2*)(Qsh + t * SP + d8);
            #pragma unroll
            for (int jj = 0; jj < 4; ++jj) {
                float2 f = __half22float2(pq[jj]);
                dst[jj] = __floats2half2_rn(f.x * e, f.y * e);
            }
        }
        {
            const int d = t;
            const __half* ps = (const __half*)&hs[qq];
            #pragma unroll
            for (int jj = 0; jj < 8; ++jj) {
                const int e = d8 + jj;
                Sth[e * SP + (d ^ (((e >> 2) & 15) << 1))] = ps[jj];
            }
        }
    }
    __syncthreads();

    const int lane = tid & 31, wid = tid >> 5;
    const int gr = lane >> 2, tg = lane & 3;
    const int wm = (wid >> 1) * 16, wn = (wid & 1) * 32;
    const int ra = wm + gr, rb = wm + 8 + gr;

    float acc[4][4];
    #pragma unroll
    for (int j = 0; j < 4; ++j)
        #pragma unroll
        for (int q = 0; q < 4; ++q) acc[j][q] = 0.f;
    {
        const __half2* Q2 = (const __half2*)Qsh;
        const __half2* St2 = (const __half2*)Sth;
        #pragma unroll
        for (int ks = 0; ks < 4; ++ks) {
            const int kh2 = ks * 8 + tg;
            uint32_t a0 = H2U(Q2[ra * SP2 + kh2]);
            uint32_t a1 = H2U(Q2[rb * SP2 + kh2]);
            uint32_t a2 = H2U(Q2[ra * SP2 + kh2 + 4]);
            uint32_t a3 = H2U(Q2[rb * SP2 + kh2 + 4]);
            #pragma unroll
            for (int j = 0; j < 4; ++j) {
                const int n = wn + j * 8 + gr;
                const int swn = (n >> 2) & 15;
                mma_f16(acc[j], a0, a1, a2, a3,
                        H2U(St2[n * SP2 + (kh2 ^ swn)]),
                        H2U(St2[n * SP2 + ((kh2 + 4) ^ swn)]));
            }
        }
    }

    #pragma unroll
    for (int j = 0; j < 4; ++j)
        #pragma unroll
        for (int qp = 0; qp < 2; ++qp) {
            const int row = wm + gr + qp * 8;
            const int col = wn + j * 8 + tg * 2;
            const int m = m0 + row;
            const float og = Og[row];
            const float2 hi = __half22float2(
                *(const __half2*)(g_hh + (size_t)m * DIM + h * 64 + col));
            const float hv0 = (acc[j][qp*2]   + hi.x) * og;
            const float hv1 = (acc[j][qp*2+1] + hi.y) * og;
            g_hfh[afrag_off(m, h * 64 + col)] = __floats2half2_rn(hv0, hv1);
        }
}

extern "C" void kernel_launch(void* const* d_in, const int* in_sizes, int n_in,
                              void* d_out, int out_size) {
    const float* x      = (const float*)d_in[0];
    const float* hidden = (const float*)d_in[1];
    const float* w_rms  = (const float*)d_in[2];
    const float* w_qkv  = (const float*)d_in[3];
    const float* w_gate = (const float*)d_in[4];
    const float* w_out  = (const float*)d_in[5];
    float* out = (float*)d_out;

    static bool attr_done = false;
    if (!attr_done) {
        cudaFuncSetAttribute(gemm_f16_kernel<0>,
            cudaFuncAttributeMaxDynamicSharedMemorySize, 65536);
        cudaFuncSetAttribute(gemm_f16_kernel<1>,
            cudaFuncAttributeMaxDynamicSharedMemorySize, 65536);
        attr_done = true;
    }

    startup_kernel<<<MTOK + PREP_BLOCKS, 256>>>(x, w_rms, w_qkv, w_gate, w_out);
    {
        dim3 grid(N1 / 128, MTOK / 128);
        gemm_f16_kernel<0><<<grid, 128, 65536>>>(nullptr, nullptr);
    }
    chunk_intra_kernel<<<TOTCHUNK, 256>>>();
    state_prefix_kernel<<<256, 256>>>(hidden);
    chunk_inter_kernel<<<TOTCHUNK, 256>>>();
    {
        dim3 grid(DIM / 128, MTOK / 128);
        gemm_f16_kernel<1><<<grid, 128, 65536>>>(x, out);
    }
}